// round 8
// baseline (speedup 1.0000x reference)
#include <cuda_runtime.h>
#include <cuda_fp16.h>
#include <math.h>
#include <stdint.h>

#define NB 4
#define LSEQ 4096
#define CC 512
#define C2 1024
#define HH 8
#define DD 64
#define ROWS (NB*LSEQ)          // 16384
#define SPLIT 16
#define SCHUNK (LSEQ/SPLIT)     // 256
#define NLAYERS 12
#define ELEMS (ROWS*CC)         // 8388608
#define ELEMS4 (ELEMS/4)

typedef __half h16;

// ---------------- device globals (no allocation) ----------------
// [2] = scratch slot (z-lane for dual self-layer launches)
__device__ float g_f0[ELEMS], g_f1[ELEMS];
__device__ float g_q[2][ELEMS], g_k[2][ELEMS], g_v[2][ELEMS], g_m[2][ELEMS];
__device__ float g_kvp[2][SPLIT*NB*HH*DD*DD];
__device__ float g_ksp[2][SPLIT*NB*HH*DD];
__device__ float g_kv[2][NB*HH*DD*DD];
__device__ float g_ksum[2][NB*HH*DD];

// fp16 hi/lo activation shadows
__device__ h16 s_xh0[ELEMS], s_xl0[ELEMS], s_xh1[ELEMS], s_xl1[ELEMS];
__device__ h16 s_mh[2][ELEMS], s_ml[2][ELEMS];
__device__ h16 s_ch0[ROWS*C2], s_cl0[ROWS*C2];
__device__ h16 s_ch1[ROWS*C2], s_cl1[ROWS*C2];
__device__ h16 s_th[2][ROWS*C2], s_tl[2][ROWS*C2];

// transposed fp16 weights: [N rows][K cols], per layer
__device__ h16 w_q[NLAYERS*CC*CC];
__device__ h16 w_k[NLAYERS*CC*CC];
__device__ h16 w_v[NLAYERS*CC*CC];
__device__ h16 w_m[NLAYERS*CC*CC];
__device__ h16 w_1[NLAYERS*C2*C2];
__device__ h16 w_2[NLAYERS*CC*C2];

// ---------------- helpers ----------------
__device__ __forceinline__ uint32_t s2u(const void* p){
  uint32_t a;
  asm("{ .reg .u64 t; cvta.to.shared.u64 t, %1; cvt.u32.u64 %0, t; }" : "=r"(a) : "l"(p));
  return a;
}

__device__ __forceinline__ void hsplit_store4(h16* H, h16* L, size_t idx,
                                              float a, float b, float c, float d){
  h16 h0=__float2half(a), h1=__float2half(b), h2=__float2half(c), h3=__float2half(d);
  h16 l0=__float2half(a-__half2float(h0));
  h16 l1=__float2half(b-__half2float(h1));
  h16 l2=__float2half(c-__half2float(h2));
  h16 l3=__float2half(d-__half2float(h3));
  *(ushort4*)(H+idx) = make_ushort4(__half_as_ushort(h0), __half_as_ushort(h1),
                                    __half_as_ushort(h2), __half_as_ushort(h3));
  *(ushort4*)(L+idx) = make_ushort4(__half_as_ushort(l0), __half_as_ushort(l1),
                                    __half_as_ushort(l2), __half_as_ushort(l3));
}

__device__ __forceinline__ void hsplit_store2(h16* H, h16* L, size_t idx, float a, float b){
  h16 h0=__float2half(a), h1=__float2half(b);
  h16 l0=__float2half(a-__half2float(h0));
  h16 l1=__float2half(b-__half2float(h1));
  *(ushort2*)(H+idx) = make_ushort2(__half_as_ushort(h0), __half_as_ushort(h1));
  *(ushort2*)(L+idx) = make_ushort2(__half_as_ushort(l0), __half_as_ushort(l1));
}

__device__ __forceinline__ void cpasync16(uint32_t dst, const void* src){
  asm volatile("cp.async.cg.shared.global [%0], [%1], 16;" :: "r"(dst), "l"(src));
}

__device__ __forceinline__ void ldsm4(uint32_t* r, uint32_t addr){
  asm volatile("ldmatrix.sync.aligned.m8n8.x4.shared.b16 {%0,%1,%2,%3}, [%4];"
    : "=r"(r[0]),"=r"(r[1]),"=r"(r[2]),"=r"(r[3]) : "r"(addr));
}

__device__ __forceinline__ void mma16816(float* d, const uint32_t* a, const uint32_t* b){
  asm volatile("mma.sync.aligned.m16n8k16.row.col.f32.f16.f16.f32 "
    "{%0,%1,%2,%3},{%4,%5,%6,%7},{%8,%9},{%0,%1,%2,%3};"
    : "+f"(d[0]),"+f"(d[1]),"+f"(d[2]),"+f"(d[3])
    : "r"(a[0]),"r"(a[1]),"r"(a[2]),"r"(a[3]), "r"(b[0]),"r"(b[1]));
}

// swizzled byte offset within a tile (rows x 32 halves; 2 rows per 128B physrow)
__device__ __forceinline__ uint32_t swoff(int row, int c){
  int pr = row >> 1;
  int ch = ((row & 1)*4 + c) ^ (pr & 7);
  return (uint32_t)(pr*128 + ch*16);
}

// ---------------- operand selectors ----------------
// A: 0=x0, 1=x1, 2=msg[0], 3=msg[1], 4=cat0, 5=cat1, 6=t[0], 7=t[1]
__device__ __forceinline__ void apair(int s, const h16*& h, const h16*& l){
  switch(s){
    case 0: h=s_xh0;    l=s_xl0;    break;
    case 1: h=s_xh1;    l=s_xl1;    break;
    case 2: h=s_mh[0];  l=s_ml[0];  break;
    case 3: h=s_mh[1];  l=s_ml[1];  break;
    case 4: h=s_ch0;    l=s_cl0;    break;
    case 5: h=s_ch1;    l=s_cl1;    break;
    case 6: h=s_th[0];  l=s_tl[0];  break;
    default:h=s_th[1];  l=s_tl[1];  break;
  }
}
__device__ __forceinline__ const h16* bsel(int s, int layer){
  switch(s){
    case 0: return w_q + (size_t)layer*CC*CC;
    case 1: return w_k + (size_t)layer*CC*CC;
    case 2: return w_v + (size_t)layer*CC*CC;
    case 3: return w_m + (size_t)layer*CC*CC;
    case 4: return w_1 + (size_t)layer*C2*C2;
    default:return w_2 + (size_t)layer*CC*C2;
  }
}
// C: slot = s>>2, kind = s&3: 0=q,1=k,2=v,3=m
__device__ __forceinline__ float* cbuf(int s){
  int slot = s >> 2;
  switch(s & 3){
    case 0: return g_q[slot]; case 1: return g_k[slot];
    case 2: return g_v[slot]; default: return g_m[slot];
  }
}

// ---------------- split-fp16 GEMM via mma.sync ----------------
// C[M,N] = epi( (Ahi+Alo)[M,K] @ B^T[N,K] ), CTA tile 128x256x32, warp 64x64, 4-stage.
// grid (N/256, M/128, nz); z selects (a0,c0)/(a1,c1).
// EPI: 0 none->fp32, 1 elu+1->fp32, 3 relu->fp16 hi/lo into t[Csel]
#define NSTG 4
#define STG_BYTES 32768
#define MMA_SMEM (NSTG*STG_BYTES)

template<int EPI>
__global__ __launch_bounds__(256)
void mma_gemm(int a0, int a1, int Bsel, int layer, int c0, int c1, int N, int K)
{
  extern __shared__ char smc[];
  const uint32_t sb = s2u(smc);
  const int z = blockIdx.z;
  const int Asel = z ? a1 : a0;
  const int Csel = z ? c1 : c0;

  const h16 *Ah,*Al;
  apair(Asel, Ah, Al);
  const h16* Bh = bsel(Bsel, layer);

  const int t = threadIdx.x, lane = t & 31, wid = t >> 5;
  const int wm = wid & 1, wn = wid >> 1;       // warp tile 64x64
  const int bm = blockIdx.y*128, bn = blockIdx.x*256;
  const int nc = K >> 5;

  const char* gAh = (const char*)(Ah + (size_t)bm*K);
  const char* gAl = (const char*)(Al + (size_t)bm*K);
  const char* gB  = (const char*)(Bh + (size_t)bn*K);

  const int lr0 = t >> 2, lc0 = t & 3;
  const int lm = lane >> 3, lrr = lane & 7;

  float acc[4][8][4];
#pragma unroll
  for (int i=0;i<4;i++)
#pragma unroll
    for (int j=0;j<8;j++)
#pragma unroll
      for (int q=0;q<4;q++) acc[i][j][q] = 0.f;

#define LOAD_STAGE(stg, ck) do {                                                  \
    uint32_t base_ = sb + (stg)*STG_BYTES;                                        \
    size_t k0_ = (size_t)(ck)*64;  /* bytes along K */                            \
    cpasync16(base_ + swoff(lr0,     lc0), gAh + (size_t)lr0     *K*2 + k0_ + lc0*16); \
    cpasync16(base_ + swoff(lr0+64,  lc0), gAh + (size_t)(lr0+64)*K*2 + k0_ + lc0*16); \
    cpasync16(base_ + 8192 + swoff(lr0,    lc0), gAl + (size_t)lr0     *K*2 + k0_ + lc0*16); \
    cpasync16(base_ + 8192 + swoff(lr0+64, lc0), gAl + (size_t)(lr0+64)*K*2 + k0_ + lc0*16); \
    cpasync16(base_ + 16384 + swoff(lr0,      lc0), gB + (size_t)lr0      *K*2 + k0_ + lc0*16); \
    cpasync16(base_ + 16384 + swoff(lr0+64,   lc0), gB + (size_t)(lr0+64) *K*2 + k0_ + lc0*16); \
    cpasync16(base_ + 16384 + swoff(lr0+128,  lc0), gB + (size_t)(lr0+128)*K*2 + k0_ + lc0*16); \
    cpasync16(base_ + 16384 + swoff(lr0+192,  lc0), gB + (size_t)(lr0+192)*K*2 + k0_ + lc0*16); \
    asm volatile("cp.async.commit_group;");                                       \
  } while(0)

  LOAD_STAGE(0, 0);
  LOAD_STAGE(1, 1);
  LOAD_STAGE(2, 2);            // nc >= 16 always

  for (int c = 0; c < nc; c++){
    if (c + 3 < nc) LOAD_STAGE((c+3)%NSTG, c+3);
    int rem = nc - 1 - c;
    if (rem >= 3)      asm volatile("cp.async.wait_group 3;" ::: "memory");
    else if (rem == 2) asm volatile("cp.async.wait_group 2;" ::: "memory");
    else if (rem == 1) asm volatile("cp.async.wait_group 1;" ::: "memory");
    else               asm volatile("cp.async.wait_group 0;" ::: "memory");
    __syncthreads();

    const uint32_t base = sb + (c%NSTG)*STG_BYTES;
#pragma unroll
    for (int k16 = 0; k16 < 2; k16++){
      uint32_t ah[4][4], al[4][4], bh[8][2];
#pragma unroll
      for (int mt = 0; mt < 4; mt++){
        int row = wm*64 + mt*16 + (lm&1)*8 + lrr;
        int ch  = k16*2 + (lm>>1);
        uint32_t o = swoff(row, ch);
        ldsm4(ah[mt], base + o);
        ldsm4(al[mt], base + 8192 + o);
      }
#pragma unroll
      for (int g = 0; g < 4; g++){
        int row = wn*64 + g*16 + (lm>>1)*8 + lrr;
        int ch  = k16*2 + (lm&1);
        uint32_t o = swoff(row, ch);
        uint32_t r4[4];
        ldsm4(r4, base + 16384 + o);
        bh[g*2][0]=r4[0]; bh[g*2][1]=r4[1]; bh[g*2+1][0]=r4[2]; bh[g*2+1][1]=r4[3];
      }
#pragma unroll
      for (int mt = 0; mt < 4; mt++)
#pragma unroll
        for (int nt = 0; nt < 8; nt++){
          mma16816(acc[mt][nt], ah[mt], bh[nt]);
          mma16816(acc[mt][nt], al[mt], bh[nt]);
        }
    }
    __syncthreads();
  }

  // ---------------- epilogue ----------------
  const int er = bm + wm*64 + (lane>>2);
  const int ec = bn + wn*64 + 2*(lane&3);
#pragma unroll
  for (int mt = 0; mt < 4; mt++){
#pragma unroll
    for (int nt = 0; nt < 8; nt++){
      int row = er + mt*16;
      int col = ec + nt*8;
      float v0 = acc[mt][nt][0], v1 = acc[mt][nt][1];
      float v2 = acc[mt][nt][2], v3 = acc[mt][nt][3];
      if (EPI == 1){
        v0 = v0 > 0.f ? v0 + 1.f : expf(v0);
        v1 = v1 > 0.f ? v1 + 1.f : expf(v1);
        v2 = v2 > 0.f ? v2 + 1.f : expf(v2);
        v3 = v3 > 0.f ? v3 + 1.f : expf(v3);
      } else if (EPI == 3){
        v0 = v0 > 0.f ? v0 : 0.f; v1 = v1 > 0.f ? v1 : 0.f;
        v2 = v2 > 0.f ? v2 : 0.f; v3 = v3 > 0.f ? v3 : 0.f;
      }
      if (EPI == 3){
        h16* TH = s_th[Csel]; h16* TL = s_tl[Csel];
        hsplit_store2(TH, TL, (size_t)row*N + col, v0, v1);
        hsplit_store2(TH, TL, (size_t)(row+8)*N + col, v2, v3);
      } else {
        float* C = cbuf(Csel);
        *(float2*)(C + (size_t)row*N + col)     = make_float2(v0, v1);
        *(float2*)(C + (size_t)(row+8)*N + col) = make_float2(v2, v3);
      }
    }
  }
}

// ---------------- weight prep: transpose + fp16 ----------------
__global__ __launch_bounds__(256)
void wprep(const float* __restrict__ W, int wsel, int K, int N)
{
  h16 *oh;
  switch(wsel){
    case 0: oh=w_q; break;
    case 1: oh=w_k; break;
    case 2: oh=w_v; break;
    case 3: oh=w_m; break;
    case 4: oh=w_1; break;
    default:oh=w_2; break;
  }
  const int l = blockIdx.z;
  const float* Wl = W + (size_t)l*K*N;
  oh += (size_t)l*(size_t)N*K;
  __shared__ float tile[32][33];
  const int k0 = blockIdx.y*32, n0 = blockIdx.x*32;
  const int tx = threadIdx.x, ty = threadIdx.y;
#pragma unroll
  for (int i = 0; i < 4; i++){
    int r = ty + i*8;
    tile[r][tx] = Wl[(size_t)(k0+r)*N + n0 + tx];
  }
  __syncthreads();
#pragma unroll
  for (int i = 0; i < 4; i++){
    int r = ty + i*8;
    oh[(size_t)(n0+r)*K + k0 + tx] = __float2half(tile[tx][r]);
  }
}

// ---------------- attention: KV split-K (deterministic) ----------------
__global__ __launch_bounds__(256)
void kv_partial(int s0, int s1)
{
  const int slot = blockIdx.z ? s1 : s0;
  const int nh = blockIdx.y, part = blockIdx.x;
  const int n = nh >> 3, h = nh & 7;
  __shared__ float Ks[32][68];
  __shared__ float Vs[32][68];
  const int t = threadIdx.x;
  const int tx = t & 15, ty = t >> 4;
  const float* Kb = g_k[slot] + (size_t)n*LSEQ*CC + h*DD;
  const float* Vb = g_v[slot] + (size_t)n*LSEQ*CC + h*DD;
  float acc[4][4] = {};
  float ksum = 0.f;
  const int send = part*SCHUNK + SCHUNK;
  for (int s0i = part*SCHUNK; s0i < send; s0i += 32){
#pragma unroll
    for (int p = 0; p < 2; p++){
      int idx = t + p*256;
      int r = idx >> 4, c4 = (idx & 15) << 2;
      *(float4*)&Ks[r][c4] = *(const float4*)(Kb + (size_t)(s0i+r)*CC + c4);
      *(float4*)&Vs[r][c4] = *(const float4*)(Vb + (size_t)(s0i+r)*CC + c4);
    }
    __syncthreads();
    if (t < DD){
#pragma unroll
      for (int kk = 0; kk < 32; kk++) ksum += Ks[kk][t];
    }
#pragma unroll
    for (int kk = 0; kk < 32; kk++){
      float4 a = *(const float4*)&Ks[kk][ty*4];
      float4 b = *(const float4*)&Vs[kk][tx*4];
      float ar[4]={a.x,a.y,a.z,a.w}, br[4]={b.x,b.y,b.z,b.w};
#pragma unroll
      for (int i=0;i<4;i++)
#pragma unroll
        for (int j=0;j<4;j++) acc[i][j] = fmaf(ar[i],br[j],acc[i][j]);
    }
    __syncthreads();
  }
  float* dst = g_kvp[slot] + ((size_t)part*NB*HH + nh)*DD*DD;
#pragma unroll
  for (int i=0;i<4;i++)
    *(float4*)&dst[(ty*4+i)*DD + tx*4] =
        make_float4(acc[i][0],acc[i][1],acc[i][2],acc[i][3]);
  if (t < DD) g_ksp[slot][(size_t)part*NB*HH*DD + nh*DD + t] = ksum;
}

__global__ __launch_bounds__(256)
void kv_reduce(int s0, int s1)
{
  const int slot = blockIdx.z ? s1 : s0;
  int i = blockIdx.x*256 + threadIdx.x;
  if (i < NB*HH*DD*DD){
    float s = 0.f;
#pragma unroll
    for (int p=0;p<SPLIT;p++) s += g_kvp[slot][(size_t)p*NB*HH*DD*DD + i];
    g_kv[slot][i] = s;
  }
  if (i < NB*HH*DD){
    float s=0.f;
#pragma unroll
    for (int p=0;p<SPLIT;p++) s += g_ksp[slot][p*NB*HH*DD + i];
    g_ksum[slot][i] = s;
  }
}

// msg = (Q @ KVu) / (Q.Ksum+eps)  -> fp16 hi/lo pair
__global__ __launch_bounds__(256)
void msg_kernel(int s0, int s1)
{
  const int slot = blockIdx.z ? s1 : s0;
  const int nh = blockIdx.y;
  const int n = nh >> 3, h = nh & 7;
  const int l0 = blockIdx.x * 64;
  __shared__ float Qs[64][68];
  __shared__ float KVs[64][68];
  __shared__ float ksm[64];
  __shared__ float zrow[64];
  const int t = threadIdx.x;
  const int tx = t & 15, ty = t >> 4;
  const float* Qb  = g_q[slot]  + (size_t)n*LSEQ*CC + h*DD;
  const float* KVb = g_kv[slot] + (size_t)nh*DD*DD;
#pragma unroll
  for (int p=0;p<4;p++){
    int idx = t + p*256;
    int r = idx >> 4, c4 = (idx & 15) << 2;
    float4 q = *(const float4*)(Qb + (size_t)(l0+r)*CC + c4);
    Qs[c4+0][r]=q.x; Qs[c4+1][r]=q.y; Qs[c4+2][r]=q.z; Qs[c4+3][r]=q.w;
    *(float4*)&KVs[r][c4] = *(const float4*)(KVb + r*DD + c4);
  }
  if (t < DD) ksm[t] = g_ksum[slot][nh*DD + t];
  __syncthreads();
  if (t < DD){
    float dn = 0.f;
#pragma unroll
    for (int d=0; d<DD; d++) dn = fmaf(Qs[d][t], ksm[d], dn);
    zrow[t] = 1.0f / (dn + 1e-6f);
  }
  __syncthreads();
  float acc[4][4] = {};
#pragma unroll
  for (int kk=0; kk<DD; kk++){
    float4 a = *(const float4*)&Qs[kk][ty*4];
    float4 b = *(const float4*)&KVs[kk][tx*4];
    float ar[4]={a.x,a.y,a.z,a.w}, br[4]={b.x,b.y,b.z,b.w};
#pragma unroll
    for (int i=0;i<4;i++)
#pragma unroll
      for (int j=0;j<4;j++) acc[i][j] = fmaf(ar[i],br[j],acc[i][j]);
  }
#pragma unroll
  for (int i=0;i<4;i++){
    int m = ty*4+i;
    float zz = zrow[m];
    size_t base = ((size_t)(n*LSEQ + l0 + m))*CC + h*DD + tx*4;
    hsplit_store4(s_mh[slot], s_ml[slot], base,
                  acc[i][0]*zz, acc[i][1]*zz, acc[i][2]*zz, acc[i][3]*zz);
  }
}

// ---------------- LN kernels ----------------
__device__ __forceinline__ void ln_core(const float4& v, int t, float& mu, float& rs)
{
  float s  = v.x+v.y+v.z+v.w;
  float s2 = v.x*v.x + v.y*v.y + v.z*v.z + v.w*v.w;
  __shared__ float sh[8];
#pragma unroll
  for (int o=16;o>0;o>>=1){
    s  += __shfl_xor_sync(0xffffffffu, s, o);
    s2 += __shfl_xor_sync(0xffffffffu, s2, o);
  }
  if ((t & 31) == 0){ sh[t>>5] = s; sh[4 + (t>>5)] = s2; }
  __syncthreads();
  s  = sh[0]+sh[1]+sh[2]+sh[3];
  s2 = sh[4]+sh[5]+sh[6]+sh[7];
  mu = s * (1.0f/CC);
  float var = s2 * (1.0f/CC) - mu*mu;
  rs = rsqrtf(var + 1e-5f);
}

// LN(g_m[slot]) -> cat{xsel}[:, 512:1024] fp16 hi/lo
__global__ __launch_bounds__(128)
void ln_to_cat(int x0, int x1, int s0, int s1,
               const float* __restrict__ gamma, const float* __restrict__ beta)
{
  const int xsel = blockIdx.z ? x1 : x0;
  const int slot = blockIdx.z ? s1 : s0;
  const int row = blockIdx.x;
  const int t = threadIdx.x;
  float4 v = *(const float4*)(g_m[slot] + (size_t)row*CC + t*4);
  float mu, rs;
  ln_core(v, t, mu, rs);
  float4 g = *(const float4*)(gamma + t*4);
  float4 b = *(const float4*)(beta + t*4);
  float o0 = (v.x-mu)*rs*g.x + b.x;
  float o1 = (v.y-mu)*rs*g.y + b.y;
  float o2 = (v.z-mu)*rs*g.z + b.z;
  float o3 = (v.w-mu)*rs*g.w + b.w;
  h16* ch = xsel ? s_ch1 : s_ch0;
  h16* cl = xsel ? s_cl1 : s_cl0;
  hsplit_store4(ch, cl, (size_t)row*C2 + CC + t*4, o0, o1, o2, o3);
}

// x = x + LN(g_k[slot]); writes fp32 x, fp16 shadow, and cat x-half
__global__ __launch_bounds__(128)
void ln_res(int x0, int x1, int s0, int s1,
            const float* __restrict__ gamma, const float* __restrict__ beta)
{
  const int xsel = blockIdx.z ? x1 : x0;
  const int slot = blockIdx.z ? s1 : s0;
  const int row = blockIdx.x;
  const int t = threadIdx.x;
  float4 v = *(const float4*)(g_k[slot] + (size_t)row*CC + t*4);
  float mu, rs;
  ln_core(v, t, mu, rs);
  float4 g = *(const float4*)(gamma + t*4);
  float4 b = *(const float4*)(beta + t*4);
  float* x = xsel ? g_f1 : g_f0;
  h16* xh = xsel ? s_xh1 : s_xh0;
  h16* xl = xsel ? s_xl1 : s_xl0;
  h16* ch = xsel ? s_ch1 : s_ch0;
  h16* cl = xsel ? s_cl1 : s_cl0;
  float4 r = *(const float4*)(x + (size_t)row*CC + t*4);
  float o0 = (v.x-mu)*rs*g.x + b.x + r.x;
  float o1 = (v.y-mu)*rs*g.y + b.y + r.y;
  float o2 = (v.z-mu)*rs*g.z + b.z + r.z;
  float o3 = (v.w-mu)*rs*g.w + b.w + r.w;
  *(float4*)(x + (size_t)row*CC + t*4) = make_float4(o0,o1,o2,o3);
  hsplit_store4(xh, xl, (size_t)row*CC + t*4, o0, o1, o2, o3);
  hsplit_store4(ch, cl, (size_t)row*C2 + t*4, o0, o1, o2, o3);
}

__global__ __launch_bounds__(256)
void copy_in(const float* __restrict__ f0, const float* __restrict__ f1)
{
  size_t i = (size_t)blockIdx.x*256 + threadIdx.x;
  float4 a = ((const float4*)f0)[i];
  float4 b = ((const float4*)f1)[i];
  ((float4*)g_f0)[i] = a;
  ((float4*)g_f1)[i] = b;
  size_t row = i >> 7, c4 = i & 127;
  hsplit_store4(s_xh0, s_xl0, i*4, a.x, a.y, a.z, a.w);
  hsplit_store4(s_xh1, s_xl1, i*4, b.x, b.y, b.z, b.w);
  hsplit_store4(s_ch0, s_cl0, row*C2 + c4*4, a.x, a.y, a.z, a.w);
  hsplit_store4(s_ch1, s_cl1, row*C2 + c4*4, b.x, b.y, b.z, b.w);
}

__global__ __launch_bounds__(256)
void copy_out(float* __restrict__ out)
{
  size_t i = (size_t)blockIdx.x*256 + threadIdx.x;
  ((float4*)out)[i]          = ((const float4*)g_f0)[i];
  ((float4*)out)[i + ELEMS4] = ((const float4*)g_f1)[i];
}

// ---------------- host-side layer drivers ----------------
// C-selector encoding: slot*4 + kind (0=q,1=k,2=v,3=m)
static void enc_dual(int layer,
                     const float* gg1, const float* bb1,
                     const float* gg2, const float* bb2)
{
  dim3 blk(256);
  dim3 gq(2, 128, 2);        // N=512
  dim3 g1k(4, 128, 2);       // N=1024
  mma_gemm<1><<<gq,  blk, MMA_SMEM>>>(0, 1, 0, layer, 0, 4, CC, CC);   // Q
  mma_gemm<1><<<gq,  blk, MMA_SMEM>>>(0, 1, 1, layer, 1, 5, CC, CC);   // K
  mma_gemm<0><<<gq,  blk, MMA_SMEM>>>(0, 1, 2, layer, 2, 6, CC, CC);   // V
  kv_partial<<<dim3(SPLIT, NB*HH, 2), blk>>>(0, 1);
  kv_reduce<<<dim3(512, 1, 2), blk>>>(0, 1);
  msg_kernel<<<dim3(LSEQ/64, NB*HH, 2), blk>>>(0, 1);
  mma_gemm<0><<<gq,  blk, MMA_SMEM>>>(2, 3, 3, layer, 3, 7, CC, CC);   // msg@Wm -> m
  ln_to_cat<<<dim3(ROWS,1,2), 128>>>(0, 1, 0, 1, gg1, bb1);
  mma_gemm<3><<<g1k, blk, MMA_SMEM>>>(4, 5, 4, layer, 0, 1, C2, C2);   // relu(cat@W1) -> t[slot]
  mma_gemm<0><<<gq,  blk, MMA_SMEM>>>(6, 7, 5, layer, 1, 5, CC, C2);   // t@W2 -> k[slot]
  ln_res<<<dim3(ROWS,1,2), 128>>>(0, 1, 0, 1, gg2, bb2);
}

static void enc_single(int xsel, int ssel, int layer,
                       const float* gg1, const float* bb1,
                       const float* gg2, const float* bb2)
{
  dim3 blk(256);
  dim3 gq(2, 128, 1);
  dim3 g1k(4, 128, 1);
  mma_gemm<1><<<gq,  blk, MMA_SMEM>>>(xsel, 0, 0, layer, 0, 0, CC, CC); // Q -> q[0]
  mma_gemm<1><<<gq,  blk, MMA_SMEM>>>(ssel, 0, 1, layer, 1, 0, CC, CC); // K -> k[0]
  mma_gemm<0><<<gq,  blk, MMA_SMEM>>>(ssel, 0, 2, layer, 2, 0, CC, CC); // V -> v[0]
  kv_partial<<<dim3(SPLIT, NB*HH, 1), blk>>>(0, 0);
  kv_reduce<<<dim3(512, 1, 1), blk>>>(0, 0);
  msg_kernel<<<dim3(LSEQ/64, NB*HH, 1), blk>>>(0, 0);
  mma_gemm<0><<<gq,  blk, MMA_SMEM>>>(2, 0, 3, layer, 3, 0, CC, CC);    // msg@Wm -> m[0]
  ln_to_cat<<<dim3(ROWS,1,1), 128>>>(xsel, 0, 0, 0, gg1, bb1);
  mma_gemm<3><<<g1k, blk, MMA_SMEM>>>(4+xsel, 0, 4, layer, 0, 0, C2, C2); // -> t[0]
  mma_gemm<0><<<gq,  blk, MMA_SMEM>>>(6, 0, 5, layer, 1, 0, CC, C2);    // -> k[0]
  ln_res<<<dim3(ROWS,1,1), 128>>>(xsel, 0, 0, 0, gg2, bb2);
}

extern "C" void kernel_launch(void* const* d_in, const int* in_sizes, int n_in,
                              void* d_out, int out_size)
{
  (void)in_sizes; (void)n_in; (void)out_size;
  const float* feat0 = (const float*)d_in[0];
  const float* feat1 = (const float*)d_in[1];
  const float* Wq = (const float*)d_in[2];
  const float* Wk = (const float*)d_in[3];
  const float* Wv = (const float*)d_in[4];
  const float* Wm = (const float*)d_in[5];
  const float* W1 = (const float*)d_in[6];
  const float* W2 = (const float*)d_in[7];
  const float* g1 = (const float*)d_in[8];
  const float* b1 = (const float*)d_in[9];
  const float* g2 = (const float*)d_in[10];
  const float* b2 = (const float*)d_in[11];

  cudaFuncSetAttribute(mma_gemm<0>, cudaFuncAttributeMaxDynamicSharedMemorySize, MMA_SMEM);
  cudaFuncSetAttribute(mma_gemm<1>, cudaFuncAttributeMaxDynamicSharedMemorySize, MMA_SMEM);
  cudaFuncSetAttribute(mma_gemm<3>, cudaFuncAttributeMaxDynamicSharedMemorySize, MMA_SMEM);

  dim3 wblk(32, 8);
  wprep<<<dim3(CC/32, CC/32, NLAYERS), wblk>>>(Wq, 0, CC, CC);
  wprep<<<dim3(CC/32, CC/32, NLAYERS), wblk>>>(Wk, 1, CC, CC);
  wprep<<<dim3(CC/32, CC/32, NLAYERS), wblk>>>(Wv, 2, CC, CC);
  wprep<<<dim3(CC/32, CC/32, NLAYERS), wblk>>>(Wm, 3, CC, CC);
  wprep<<<dim3(C2/32, C2/32, NLAYERS), wblk>>>(W1, 4, C2, C2);
  wprep<<<dim3(CC/32, C2/32, NLAYERS), wblk>>>(W2, 5, C2, CC);

  copy_in<<<ELEMS4/256, 256>>>(feat0, feat1);

  for (int i = 0; i < NLAYERS; i++){
    const float* gg1 = g1 + (size_t)i*CC;
    const float* bb1 = b1 + (size_t)i*CC;
    const float* gg2 = g2 + (size_t)i*CC;
    const float* bb2 = b2 + (size_t)i*CC;
    if ((i & 1) == 0){  // self: feat0 and feat1 independent, same weights
      enc_dual(i, gg1, bb1, gg2, bb2);
    } else {            // cross (sequential: feat1 sees updated feat0)
      enc_single(0, 1, i, gg1, bb1, gg2, bb2);
      enc_single(1, 0, i, gg1, bb1, gg2, bb2);
    }
  }

  copy_out<<<ELEMS4/256, 256>>>((float*)d_out);
}

// round 9
// speedup vs baseline: 1.1325x; 1.1325x over previous
#include <cuda_runtime.h>
#include <cuda_fp16.h>
#include <math.h>
#include <stdint.h>

#define NB 4
#define LSEQ 4096
#define CC 512
#define C2 1024
#define HH 8
#define DD 64
#define ROWS (NB*LSEQ)          // 16384
#define SPLIT 16
#define SCHUNK (LSEQ/SPLIT)     // 256
#define NLAYERS 12
#define ELEMS (ROWS*CC)         // 8388608
#define ELEMS4 (ELEMS/4)

typedef __half h16;

// ---------------- device globals (no allocation) ----------------
// [2] = scratch slot (z-lane for dual self-layer launches)
__device__ float g_f0[ELEMS], g_f1[ELEMS];
__device__ float g_q[2][ELEMS], g_k[2][ELEMS], g_v[2][ELEMS], g_m[2][ELEMS];
__device__ float g_kvp[2][SPLIT*NB*HH*DD*DD];
__device__ float g_ksp[2][SPLIT*NB*HH*DD];
__device__ float g_kv[2][NB*HH*DD*DD];
__device__ float g_ksum[2][NB*HH*DD];

// fp16 hi/lo activation shadows
__device__ h16 s_xh0[ELEMS], s_xl0[ELEMS], s_xh1[ELEMS], s_xl1[ELEMS];
__device__ h16 s_mh[2][ELEMS], s_ml[2][ELEMS];
__device__ h16 s_ch0[ROWS*C2], s_cl0[ROWS*C2];
__device__ h16 s_ch1[ROWS*C2], s_cl1[ROWS*C2];
__device__ h16 s_th[2][ROWS*C2], s_tl[2][ROWS*C2];

// transposed fp16 weights: [N rows][K cols], per layer
__device__ h16 w_q[NLAYERS*CC*CC];
__device__ h16 w_k[NLAYERS*CC*CC];
__device__ h16 w_v[NLAYERS*CC*CC];
__device__ h16 w_m[NLAYERS*CC*CC];
__device__ h16 w_1[NLAYERS*C2*C2];
__device__ h16 w_2[NLAYERS*CC*C2];

// ---------------- helpers ----------------
__device__ __forceinline__ uint32_t s2u(const void* p){
  uint32_t a;
  asm("{ .reg .u64 t; cvta.to.shared.u64 t, %1; cvt.u32.u64 %0, t; }" : "=r"(a) : "l"(p));
  return a;
}

__device__ __forceinline__ void hsplit_store4(h16* H, h16* L, size_t idx,
                                              float a, float b, float c, float d){
  h16 h0=__float2half(a), h1=__float2half(b), h2=__float2half(c), h3=__float2half(d);
  h16 l0=__float2half(a-__half2float(h0));
  h16 l1=__float2half(b-__half2float(h1));
  h16 l2=__float2half(c-__half2float(h2));
  h16 l3=__float2half(d-__half2float(h3));
  *(ushort4*)(H+idx) = make_ushort4(__half_as_ushort(h0), __half_as_ushort(h1),
                                    __half_as_ushort(h2), __half_as_ushort(h3));
  *(ushort4*)(L+idx) = make_ushort4(__half_as_ushort(l0), __half_as_ushort(l1),
                                    __half_as_ushort(l2), __half_as_ushort(l3));
}

__device__ __forceinline__ void hsplit_store2(h16* H, h16* L, size_t idx, float a, float b){
  h16 h0=__float2half(a), h1=__float2half(b);
  h16 l0=__float2half(a-__half2float(h0));
  h16 l1=__float2half(b-__half2float(h1));
  *(ushort2*)(H+idx) = make_ushort2(__half_as_ushort(h0), __half_as_ushort(h1));
  *(ushort2*)(L+idx) = make_ushort2(__half_as_ushort(l0), __half_as_ushort(l1));
}

__device__ __forceinline__ void cpasync16(uint32_t dst, const void* src){
  asm volatile("cp.async.cg.shared.global [%0], [%1], 16;" :: "r"(dst), "l"(src));
}

__device__ __forceinline__ void ldsm4(uint32_t* r, uint32_t addr){
  asm volatile("ldmatrix.sync.aligned.m8n8.x4.shared.b16 {%0,%1,%2,%3}, [%4];"
    : "=r"(r[0]),"=r"(r[1]),"=r"(r[2]),"=r"(r[3]) : "r"(addr));
}

__device__ __forceinline__ void mma16816(float* d, const uint32_t* a, const uint32_t* b){
  asm volatile("mma.sync.aligned.m16n8k16.row.col.f32.f16.f16.f32 "
    "{%0,%1,%2,%3},{%4,%5,%6,%7},{%8,%9},{%0,%1,%2,%3};"
    : "+f"(d[0]),"+f"(d[1]),"+f"(d[2]),"+f"(d[3])
    : "r"(a[0]),"r"(a[1]),"r"(a[2]),"r"(a[3]), "r"(b[0]),"r"(b[1]));
}

// swizzled byte offset within an 8KB tile (128 rows x 32 halves; 2 rows per 128B physrow)
__device__ __forceinline__ uint32_t swoff(int row, int c){
  int pr = row >> 1;
  int ch = ((row & 1)*4 + c) ^ (pr & 7);
  return (uint32_t)(pr*128 + ch*16);
}

// ---------------- operand selectors ----------------
// A: 0=x0, 1=x1, 2=msg[0], 3=msg[1], 4=cat0, 5=cat1, 6=t[0], 7=t[1]
__device__ __forceinline__ void apair(int s, const h16*& h, const h16*& l){
  switch(s){
    case 0: h=s_xh0;    l=s_xl0;    break;
    case 1: h=s_xh1;    l=s_xl1;    break;
    case 2: h=s_mh[0];  l=s_ml[0];  break;
    case 3: h=s_mh[1];  l=s_ml[1];  break;
    case 4: h=s_ch0;    l=s_cl0;    break;
    case 5: h=s_ch1;    l=s_cl1;    break;
    case 6: h=s_th[0];  l=s_tl[0];  break;
    default:h=s_th[1];  l=s_tl[1];  break;
  }
}
__device__ __forceinline__ const h16* bsel(int s, int layer){
  switch(s){
    case 0: return w_q + (size_t)layer*CC*CC;
    case 1: return w_k + (size_t)layer*CC*CC;
    case 2: return w_v + (size_t)layer*CC*CC;
    case 3: return w_m + (size_t)layer*CC*CC;
    case 4: return w_1 + (size_t)layer*C2*C2;
    default:return w_2 + (size_t)layer*CC*C2;
  }
}
// C: slot = s>>2, kind = s&3: 0=q,1=k,2=v,3=m
__device__ __forceinline__ float* cbuf(int s){
  int slot = s >> 2;
  switch(s & 3){
    case 0: return g_q[slot]; case 1: return g_k[slot];
    case 2: return g_v[slot]; default: return g_m[slot];
  }
}

// ---------------- split-fp16 GEMM via mma.sync ----------------
// C[M,N] = epi( (Ahi+Alo)[M,K] @ B^T[N,K] ), CTA 128x128x32, warp 64x32, 4-stage.
// grid (N/128, M/128, nz); z selects (a0,c0)/(a1,c1).
// EPI: 0 none->fp32, 1 elu+1->fp32, 3 relu->fp16 hi/lo into t[Csel]
#define NSTG 4
#define STG_BYTES 24576
#define MMA_SMEM (NSTG*STG_BYTES)

template<int EPI>
__global__ __launch_bounds__(256)
void mma_gemm(int a0, int a1, int Bsel, int layer, int c0, int c1, int N, int K)
{
  extern __shared__ char smc[];
  const uint32_t sb = s2u(smc);
  const int z = blockIdx.z;
  const int Asel = z ? a1 : a0;
  const int Csel = z ? c1 : c0;

  const h16 *Ah,*Al;
  apair(Asel, Ah, Al);
  const h16* Bh = bsel(Bsel, layer);

  const int t = threadIdx.x, lane = t & 31, wid = t >> 5;
  const int wm = wid & 1, wn = wid >> 1;       // warp tile 64x32
  const int bm = blockIdx.y*128, bn = blockIdx.x*128;
  const int nc = K >> 5;

  const h16* gsrc[3];
  gsrc[0] = Ah + (size_t)bm*K;
  gsrc[1] = Al + (size_t)bm*K;
  gsrc[2] = Bh + (size_t)bn*K;

  const int lr0 = t >> 2, lc0 = t & 3;
  const int lm = lane >> 3, lrr = lane & 7;

  float acc[4][4][4];
#pragma unroll
  for (int i=0;i<4;i++)
#pragma unroll
    for (int j=0;j<4;j++)
#pragma unroll
      for (int q=0;q<4;q++) acc[i][j][q] = 0.f;

#define LOAD_STAGE(stg, ck) do {                                              \
    uint32_t base_ = sb + (stg)*STG_BYTES;                                    \
    int k0_ = (ck)*32;                                                        \
    _Pragma("unroll")                                                         \
    for (int tl_=0; tl_<3; tl_++){                                            \
      uint32_t tb_ = base_ + tl_*8192;                                        \
      const char* g_ = (const char*)(gsrc[tl_] + k0_);                        \
      cpasync16(tb_ + swoff(lr0,    lc0), g_ + ((size_t)lr0   *K + lc0*8)*2); \
      cpasync16(tb_ + swoff(lr0+64, lc0), g_ + ((size_t)(lr0+64)*K + lc0*8)*2);\
    }                                                                         \
    asm volatile("cp.async.commit_group;");                                   \
  } while(0)

  LOAD_STAGE(0, 0);
  LOAD_STAGE(1, 1);
  LOAD_STAGE(2, 2);            // nc >= 16 always

  for (int c = 0; c < nc; c++){
    if (c + 3 < nc) LOAD_STAGE((c+3)%NSTG, c+3);
    int rem = nc - 1 - c;
    if (rem >= 3)      asm volatile("cp.async.wait_group 3;" ::: "memory");
    else if (rem == 2) asm volatile("cp.async.wait_group 2;" ::: "memory");
    else if (rem == 1) asm volatile("cp.async.wait_group 1;" ::: "memory");
    else               asm volatile("cp.async.wait_group 0;" ::: "memory");
    __syncthreads();

    const uint32_t base = sb + (c%NSTG)*STG_BYTES;
#pragma unroll
    for (int k16 = 0; k16 < 2; k16++){
      uint32_t ah[4][4], al[4][4], bh[4][2];
#pragma unroll
      for (int mt = 0; mt < 4; mt++){
        int row = wm*64 + mt*16 + (lm&1)*8 + lrr;
        int ch  = k16*2 + (lm>>1);
        uint32_t o = swoff(row, ch);
        ldsm4(ah[mt], base + o);
        ldsm4(al[mt], base + 8192 + o);
      }
#pragma unroll
      for (int g = 0; g < 2; g++){
        int row = wn*32 + g*16 + (lm>>1)*8 + lrr;
        int ch  = k16*2 + (lm&1);
        uint32_t o = swoff(row, ch);
        uint32_t r4[4];
        ldsm4(r4, base + 16384 + o);
        bh[g*2][0]=r4[0]; bh[g*2][1]=r4[1]; bh[g*2+1][0]=r4[2]; bh[g*2+1][1]=r4[3];
      }
#pragma unroll
      for (int mt = 0; mt < 4; mt++)
#pragma unroll
        for (int nt = 0; nt < 4; nt++){
          mma16816(acc[mt][nt], ah[mt], bh[nt]);
          mma16816(acc[mt][nt], al[mt], bh[nt]);
        }
    }
    __syncthreads();
  }

  // ---------------- epilogue ----------------
  const int er = bm + wm*64 + (lane>>2);
  const int ec = bn + wn*32 + 2*(lane&3);
#pragma unroll
  for (int mt = 0; mt < 4; mt++){
#pragma unroll
    for (int nt = 0; nt < 4; nt++){
      int row = er + mt*16;
      int col = ec + nt*8;
      float v0 = acc[mt][nt][0], v1 = acc[mt][nt][1];
      float v2 = acc[mt][nt][2], v3 = acc[mt][nt][3];
      if (EPI == 1){
        v0 = v0 > 0.f ? v0 + 1.f : expf(v0);
        v1 = v1 > 0.f ? v1 + 1.f : expf(v1);
        v2 = v2 > 0.f ? v2 + 1.f : expf(v2);
        v3 = v3 > 0.f ? v3 + 1.f : expf(v3);
      } else if (EPI == 3){
        v0 = v0 > 0.f ? v0 : 0.f; v1 = v1 > 0.f ? v1 : 0.f;
        v2 = v2 > 0.f ? v2 : 0.f; v3 = v3 > 0.f ? v3 : 0.f;
      }
      if (EPI == 3){
        h16* TH = s_th[Csel]; h16* TL = s_tl[Csel];
        hsplit_store2(TH, TL, (size_t)row*N + col, v0, v1);
        hsplit_store2(TH, TL, (size_t)(row+8)*N + col, v2, v3);
      } else {
        float* C = cbuf(Csel);
        *(float2*)(C + (size_t)row*N + col)     = make_float2(v0, v1);
        *(float2*)(C + (size_t)(row+8)*N + col) = make_float2(v2, v3);
      }
    }
  }
}

// ---------------- weight prep: transpose + fp16 ----------------
__global__ __launch_bounds__(256)
void wprep(const float* __restrict__ W, int wsel, int K, int N)
{
  h16 *oh;
  switch(wsel){
    case 0: oh=w_q; break;
    case 1: oh=w_k; break;
    case 2: oh=w_v; break;
    case 3: oh=w_m; break;
    case 4: oh=w_1; break;
    default:oh=w_2; break;
  }
  const int l = blockIdx.z;
  const float* Wl = W + (size_t)l*K*N;
  oh += (size_t)l*(size_t)N*K;
  __shared__ float tile[32][33];
  const int k0 = blockIdx.y*32, n0 = blockIdx.x*32;
  const int tx = threadIdx.x, ty = threadIdx.y;
#pragma unroll
  for (int i = 0; i < 4; i++){
    int r = ty + i*8;
    tile[r][tx] = Wl[(size_t)(k0+r)*N + n0 + tx];
  }
  __syncthreads();
#pragma unroll
  for (int i = 0; i < 4; i++){
    int r = ty + i*8;
    oh[(size_t)(n0+r)*K + k0 + tx] = __float2half(tile[tx][r]);
  }
}

// ---------------- attention: KV split-K (deterministic) ----------------
__global__ __launch_bounds__(256)
void kv_partial(int s0, int s1)
{
  const int slot = blockIdx.z ? s1 : s0;
  const int nh = blockIdx.y, part = blockIdx.x;
  const int n = nh >> 3, h = nh & 7;
  __shared__ float Ks[32][68];
  __shared__ float Vs[32][68];
  const int t = threadIdx.x;
  const int tx = t & 15, ty = t >> 4;
  const float* Kb = g_k[slot] + (size_t)n*LSEQ*CC + h*DD;
  const float* Vb = g_v[slot] + (size_t)n*LSEQ*CC + h*DD;
  float acc[4][4] = {};
  float ksum = 0.f;
  const int send = part*SCHUNK + SCHUNK;
  for (int s0i = part*SCHUNK; s0i < send; s0i += 32){
#pragma unroll
    for (int p = 0; p < 2; p++){
      int idx = t + p*256;
      int r = idx >> 4, c4 = (idx & 15) << 2;
      *(float4*)&Ks[r][c4] = *(const float4*)(Kb + (size_t)(s0i+r)*CC + c4);
      *(float4*)&Vs[r][c4] = *(const float4*)(Vb + (size_t)(s0i+r)*CC + c4);
    }
    __syncthreads();
    if (t < DD){
#pragma unroll
      for (int kk = 0; kk < 32; kk++) ksum += Ks[kk][t];
    }
#pragma unroll
    for (int kk = 0; kk < 32; kk++){
      float4 a = *(const float4*)&Ks[kk][ty*4];
      float4 b = *(const float4*)&Vs[kk][tx*4];
      float ar[4]={a.x,a.y,a.z,a.w}, br[4]={b.x,b.y,b.z,b.w};
#pragma unroll
      for (int i=0;i<4;i++)
#pragma unroll
        for (int j=0;j<4;j++) acc[i][j] = fmaf(ar[i],br[j],acc[i][j]);
    }
    __syncthreads();
  }
  float* dst = g_kvp[slot] + ((size_t)part*NB*HH + nh)*DD*DD;
#pragma unroll
  for (int i=0;i<4;i++)
    *(float4*)&dst[(ty*4+i)*DD + tx*4] =
        make_float4(acc[i][0],acc[i][1],acc[i][2],acc[i][3]);
  if (t < DD) g_ksp[slot][(size_t)part*NB*HH*DD + nh*DD + t] = ksum;
}

__global__ __launch_bounds__(256)
void kv_reduce(int s0, int s1)
{
  const int slot = blockIdx.z ? s1 : s0;
  int i = blockIdx.x*256 + threadIdx.x;
  if (i < NB*HH*DD*DD){
    float s = 0.f;
#pragma unroll
    for (int p=0;p<SPLIT;p++) s += g_kvp[slot][(size_t)p*NB*HH*DD*DD + i];
    g_kv[slot][i] = s;
  }
  if (i < NB*HH*DD){
    float s=0.f;
#pragma unroll
    for (int p=0;p<SPLIT;p++) s += g_ksp[slot][p*NB*HH*DD + i];
    g_ksum[slot][i] = s;
  }
}

// msg = (Q @ KVu) / (Q.Ksum+eps)  -> fp16 hi/lo pair
__global__ __launch_bounds__(256)
void msg_kernel(int s0, int s1)
{
  const int slot = blockIdx.z ? s1 : s0;
  const int nh = blockIdx.y;
  const int n = nh >> 3, h = nh & 7;
  const int l0 = blockIdx.x * 64;
  __shared__ float Qs[64][68];
  __shared__ float KVs[64][68];
  __shared__ float ksm[64];
  __shared__ float zrow[64];
  const int t = threadIdx.x;
  const int tx = t & 15, ty = t >> 4;
  const float* Qb  = g_q[slot]  + (size_t)n*LSEQ*CC + h*DD;
  const float* KVb = g_kv[slot] + (size_t)nh*DD*DD;
#pragma unroll
  for (int p=0;p<4;p++){
    int idx = t + p*256;
    int r = idx >> 4, c4 = (idx & 15) << 2;
    float4 q = *(const float4*)(Qb + (size_t)(l0+r)*CC + c4);
    Qs[c4+0][r]=q.x; Qs[c4+1][r]=q.y; Qs[c4+2][r]=q.z; Qs[c4+3][r]=q.w;
    *(float4*)&KVs[r][c4] = *(const float4*)(KVb + r*DD + c4);
  }
  if (t < DD) ksm[t] = g_ksum[slot][nh*DD + t];
  __syncthreads();
  if (t < DD){
    float dn = 0.f;
#pragma unroll
    for (int d=0; d<DD; d++) dn = fmaf(Qs[d][t], ksm[d], dn);
    zrow[t] = 1.0f / (dn + 1e-6f);
  }
  __syncthreads();
  float acc[4][4] = {};
#pragma unroll
  for (int kk=0; kk<DD; kk++){
    float4 a = *(const float4*)&Qs[kk][ty*4];
    float4 b = *(const float4*)&KVs[kk][tx*4];
    float ar[4]={a.x,a.y,a.z,a.w}, br[4]={b.x,b.y,b.z,b.w};
#pragma unroll
    for (int i=0;i<4;i++)
#pragma unroll
      for (int j=0;j<4;j++) acc[i][j] = fmaf(ar[i],br[j],acc[i][j]);
  }
#pragma unroll
  for (int i=0;i<4;i++){
    int m = ty*4+i;
    float zz = zrow[m];
    size_t base = ((size_t)(n*LSEQ + l0 + m))*CC + h*DD + tx*4;
    hsplit_store4(s_mh[slot], s_ml[slot], base,
                  acc[i][0]*zz, acc[i][1]*zz, acc[i][2]*zz, acc[i][3]*zz);
  }
}

// ---------------- LN kernels ----------------
__device__ __forceinline__ void ln_core(const float4& v, int t, float& mu, float& rs)
{
  float s  = v.x+v.y+v.z+v.w;
  float s2 = v.x*v.x + v.y*v.y + v.z*v.z + v.w*v.w;
  __shared__ float sh[8];
#pragma unroll
  for (int o=16;o>0;o>>=1){
    s  += __shfl_xor_sync(0xffffffffu, s, o);
    s2 += __shfl_xor_sync(0xffffffffu, s2, o);
  }
  if ((t & 31) == 0){ sh[t>>5] = s; sh[4 + (t>>5)] = s2; }
  __syncthreads();
  s  = sh[0]+sh[1]+sh[2]+sh[3];
  s2 = sh[4]+sh[5]+sh[6]+sh[7];
  mu = s * (1.0f/CC);
  float var = s2 * (1.0f/CC) - mu*mu;
  rs = rsqrtf(var + 1e-5f);
}

// LN(g_m[slot]) -> cat{xsel}[:, 512:1024] fp16 hi/lo
__global__ __launch_bounds__(128)
void ln_to_cat(int x0, int x1, int s0, int s1,
               const float* __restrict__ gamma, const float* __restrict__ beta)
{
  const int xsel = blockIdx.z ? x1 : x0;
  const int slot = blockIdx.z ? s1 : s0;
  const int row = blockIdx.x;
  const int t = threadIdx.x;
  float4 v = *(const float4*)(g_m[slot] + (size_t)row*CC + t*4);
  float mu, rs;
  ln_core(v, t, mu, rs);
  float4 g = *(const float4*)(gamma + t*4);
  float4 b = *(const float4*)(beta + t*4);
  float o0 = (v.x-mu)*rs*g.x + b.x;
  float o1 = (v.y-mu)*rs*g.y + b.y;
  float o2 = (v.z-mu)*rs*g.z + b.z;
  float o3 = (v.w-mu)*rs*g.w + b.w;
  h16* ch = xsel ? s_ch1 : s_ch0;
  h16* cl = xsel ? s_cl1 : s_cl0;
  hsplit_store4(ch, cl, (size_t)row*C2 + CC + t*4, o0, o1, o2, o3);
}

// x = x + LN(g_k[slot]); writes fp32 x, fp16 shadow, and cat x-half
__global__ __launch_bounds__(128)
void ln_res(int x0, int x1, int s0, int s1,
            const float* __restrict__ gamma, const float* __restrict__ beta)
{
  const int xsel = blockIdx.z ? x1 : x0;
  const int slot = blockIdx.z ? s1 : s0;
  const int row = blockIdx.x;
  const int t = threadIdx.x;
  float4 v = *(const float4*)(g_k[slot] + (size_t)row*CC + t*4);
  float mu, rs;
  ln_core(v, t, mu, rs);
  float4 g = *(const float4*)(gamma + t*4);
  float4 b = *(const float4*)(beta + t*4);
  float* x = xsel ? g_f1 : g_f0;
  h16* xh = xsel ? s_xh1 : s_xh0;
  h16* xl = xsel ? s_xl1 : s_xl0;
  h16* ch = xsel ? s_ch1 : s_ch0;
  h16* cl = xsel ? s_cl1 : s_cl0;
  float4 r = *(const float4*)(x + (size_t)row*CC + t*4);
  float o0 = (v.x-mu)*rs*g.x + b.x + r.x;
  float o1 = (v.y-mu)*rs*g.y + b.y + r.y;
  float o2 = (v.z-mu)*rs*g.z + b.z + r.z;
  float o3 = (v.w-mu)*rs*g.w + b.w + r.w;
  *(float4*)(x + (size_t)row*CC + t*4) = make_float4(o0,o1,o2,o3);
  hsplit_store4(xh, xl, (size_t)row*CC + t*4, o0, o1, o2, o3);
  hsplit_store4(ch, cl, (size_t)row*C2 + t*4, o0, o1, o2, o3);
}

__global__ __launch_bounds__(256)
void copy_in(const float* __restrict__ f0, const float* __restrict__ f1)
{
  size_t i = (size_t)blockIdx.x*256 + threadIdx.x;
  float4 a = ((const float4*)f0)[i];
  float4 b = ((const float4*)f1)[i];
  ((float4*)g_f0)[i] = a;
  ((float4*)g_f1)[i] = b;
  size_t row = i >> 7, c4 = i & 127;
  hsplit_store4(s_xh0, s_xl0, i*4, a.x, a.y, a.z, a.w);
  hsplit_store4(s_xh1, s_xl1, i*4, b.x, b.y, b.z, b.w);
  hsplit_store4(s_ch0, s_cl0, row*C2 + c4*4, a.x, a.y, a.z, a.w);
  hsplit_store4(s_ch1, s_cl1, row*C2 + c4*4, b.x, b.y, b.z, b.w);
}

__global__ __launch_bounds__(256)
void copy_out(float* __restrict__ out)
{
  size_t i = (size_t)blockIdx.x*256 + threadIdx.x;
  ((float4*)out)[i]          = ((const float4*)g_f0)[i];
  ((float4*)out)[i + ELEMS4] = ((const float4*)g_f1)[i];
}

// ---------------- host-side layer drivers ----------------
// C-selector encoding: slot*4 + kind (0=q,1=k,2=v,3=m)
static void enc_dual(int layer,
                     const float* gg1, const float* bb1,
                     const float* gg2, const float* bb2)
{
  dim3 blk(256);
  dim3 gq(4, 128, 2);        // N=512
  dim3 g1k(8, 128, 2);       // N=1024
  mma_gemm<1><<<gq,  blk, MMA_SMEM>>>(0, 1, 0, layer, 0, 4, CC, CC);   // Q
  mma_gemm<1><<<gq,  blk, MMA_SMEM>>>(0, 1, 1, layer, 1, 5, CC, CC);   // K
  mma_gemm<0><<<gq,  blk, MMA_SMEM>>>(0, 1, 2, layer, 2, 6, CC, CC);   // V
  kv_partial<<<dim3(SPLIT, NB*HH, 2), blk>>>(0, 1);
  kv_reduce<<<dim3(512, 1, 2), blk>>>(0, 1);
  msg_kernel<<<dim3(LSEQ/64, NB*HH, 2), blk>>>(0, 1);
  mma_gemm<0><<<gq,  blk, MMA_SMEM>>>(2, 3, 3, layer, 3, 7, CC, CC);   // msg@Wm -> m
  ln_to_cat<<<dim3(ROWS,1,2), 128>>>(0, 1, 0, 1, gg1, bb1);
  mma_gemm<3><<<g1k, blk, MMA_SMEM>>>(4, 5, 4, layer, 0, 1, C2, C2);   // relu(cat@W1) -> t[slot]
  mma_gemm<0><<<gq,  blk, MMA_SMEM>>>(6, 7, 5, layer, 1, 5, CC, C2);   // t@W2 -> k[slot]
  ln_res<<<dim3(ROWS,1,2), 128>>>(0, 1, 0, 1, gg2, bb2);
}

static void enc_single(int xsel, int ssel, int layer,
                       const float* gg1, const float* bb1,
                       const float* gg2, const float* bb2)
{
  dim3 blk(256);
  dim3 gq(4, 128, 1);
  dim3 g1k(8, 128, 1);
  mma_gemm<1><<<gq,  blk, MMA_SMEM>>>(xsel, 0, 0, layer, 0, 0, CC, CC); // Q -> q[0]
  mma_gemm<1><<<gq,  blk, MMA_SMEM>>>(ssel, 0, 1, layer, 1, 0, CC, CC); // K -> k[0]
  mma_gemm<0><<<gq,  blk, MMA_SMEM>>>(ssel, 0, 2, layer, 2, 0, CC, CC); // V -> v[0]
  kv_partial<<<dim3(SPLIT, NB*HH, 1), blk>>>(0, 0);
  kv_reduce<<<dim3(512, 1, 1), blk>>>(0, 0);
  msg_kernel<<<dim3(LSEQ/64, NB*HH, 1), blk>>>(0, 0);
  mma_gemm<0><<<gq,  blk, MMA_SMEM>>>(2, 0, 3, layer, 3, 0, CC, CC);    // msg@Wm -> m[0]
  ln_to_cat<<<dim3(ROWS,1,1), 128>>>(xsel, 0, 0, 0, gg1, bb1);
  mma_gemm<3><<<g1k, blk, MMA_SMEM>>>(4+xsel, 0, 4, layer, 0, 0, C2, C2); // -> t[0]
  mma_gemm<0><<<gq,  blk, MMA_SMEM>>>(6, 0, 5, layer, 1, 0, CC, C2);    // -> k[0]
  ln_res<<<dim3(ROWS,1,1), 128>>>(xsel, 0, 0, 0, gg2, bb2);
}

extern "C" void kernel_launch(void* const* d_in, const int* in_sizes, int n_in,
                              void* d_out, int out_size)
{
  (void)in_sizes; (void)n_in; (void)out_size;
  const float* feat0 = (const float*)d_in[0];
  const float* feat1 = (const float*)d_in[1];
  const float* Wq = (const float*)d_in[2];
  const float* Wk = (const float*)d_in[3];
  const float* Wv = (const float*)d_in[4];
  const float* Wm = (const float*)d_in[5];
  const float* W1 = (const float*)d_in[6];
  const float* W2 = (const float*)d_in[7];
  const float* g1 = (const float*)d_in[8];
  const float* b1 = (const float*)d_in[9];
  const float* g2 = (const float*)d_in[10];
  const float* b2 = (const float*)d_in[11];

  cudaFuncSetAttribute(mma_gemm<0>, cudaFuncAttributeMaxDynamicSharedMemorySize, MMA_SMEM);
  cudaFuncSetAttribute(mma_gemm<1>, cudaFuncAttributeMaxDynamicSharedMemorySize, MMA_SMEM);
  cudaFuncSetAttribute(mma_gemm<3>, cudaFuncAttributeMaxDynamicSharedMemorySize, MMA_SMEM);

  dim3 wblk(32, 8);
  wprep<<<dim3(CC/32, CC/32, NLAYERS), wblk>>>(Wq, 0, CC, CC);
  wprep<<<dim3(CC/32, CC/32, NLAYERS), wblk>>>(Wk, 1, CC, CC);
  wprep<<<dim3(CC/32, CC/32, NLAYERS), wblk>>>(Wv, 2, CC, CC);
  wprep<<<dim3(CC/32, CC/32, NLAYERS), wblk>>>(Wm, 3, CC, CC);
  wprep<<<dim3(C2/32, C2/32, NLAYERS), wblk>>>(W1, 4, C2, C2);
  wprep<<<dim3(CC/32, C2/32, NLAYERS), wblk>>>(W2, 5, C2, CC);

  copy_in<<<ELEMS4/256, 256>>>(feat0, feat1);

  for (int i = 0; i < NLAYERS; i++){
    const float* gg1 = g1 + (size_t)i*CC;
    const float* bb1 = b1 + (size_t)i*CC;
    const float* gg2 = g2 + (size_t)i*CC;
    const float* bb2 = b2 + (size_t)i*CC;
    if ((i & 1) == 0){  // self: feat0 and feat1 independent, same weights
      enc_dual(i, gg1, bb1, gg2, bb2);
    } else {            // cross (sequential: feat1 sees updated feat0)
      enc_single(0, 1, i, gg1, bb1, gg2, bb2);
      enc_single(1, 0, i, gg1, bb1, gg2, bb2);
    }
  }

  copy_out<<<ELEMS4/256, 256>>>((float*)d_out);
}

// round 10
// speedup vs baseline: 1.1518x; 1.0170x over previous
#include <cuda_runtime.h>
#include <cuda_fp16.h>
#include <math.h>
#include <stdint.h>

#define NB 4
#define LSEQ 4096
#define CC 512
#define C2 1024
#define HH 8
#define DD 64
#define ROWS (NB*LSEQ)          // 16384
#define SPLIT 16
#define SCHUNK (LSEQ/SPLIT)     // 256
#define NLAYERS 12
#define ELEMS (ROWS*CC)         // 8388608
#define ELEMS4 (ELEMS/4)
#define NQKV 1536

typedef __half h16;

// ---------------- device globals (no allocation) ----------------
__device__ float g_f0[ELEMS], g_f1[ELEMS];
__device__ float g_q[2][ELEMS], g_k[2][ELEMS], g_v[2][ELEMS], g_m[2][ELEMS];
__device__ float g_kvp[2][SPLIT*NB*HH*DD*DD];
__device__ float g_ksp[2][SPLIT*NB*HH*DD];
__device__ float g_kv[2][NB*HH*DD*DD];
__device__ float g_ksum[2][NB*HH*DD];

// fp16 hi/lo activation shadows
__device__ h16 s_xh0[ELEMS], s_xl0[ELEMS], s_xh1[ELEMS], s_xl1[ELEMS];
__device__ h16 s_mh[2][ELEMS], s_ml[2][ELEMS];
__device__ h16 s_ch0[ROWS*C2], s_cl0[ROWS*C2];
__device__ h16 s_ch1[ROWS*C2], s_cl1[ROWS*C2];
__device__ h16 s_th[2][ROWS*C2], s_tl[2][ROWS*C2];

// transposed fp16 weights: [N rows][K cols], per layer
__device__ h16 w_qkv[NLAYERS*NQKV*CC];   // rows 0-511 Wq, 512-1023 Wk, 1024-1535 Wv
__device__ h16 w_m[NLAYERS*CC*CC];
__device__ h16 w_1[NLAYERS*C2*C2];
__device__ h16 w_2[NLAYERS*CC*C2];

// ---------------- helpers ----------------
__device__ __forceinline__ uint32_t s2u(const void* p){
  uint32_t a;
  asm("{ .reg .u64 t; cvta.to.shared.u64 t, %1; cvt.u32.u64 %0, t; }" : "=r"(a) : "l"(p));
  return a;
}

__device__ __forceinline__ void hsplit_store4(h16* H, h16* L, size_t idx,
                                              float a, float b, float c, float d){
  h16 h0=__float2half(a), h1=__float2half(b), h2=__float2half(c), h3=__float2half(d);
  h16 l0=__float2half(a-__half2float(h0));
  h16 l1=__float2half(b-__half2float(h1));
  h16 l2=__float2half(c-__half2float(h2));
  h16 l3=__float2half(d-__half2float(h3));
  *(ushort4*)(H+idx) = make_ushort4(__half_as_ushort(h0), __half_as_ushort(h1),
                                    __half_as_ushort(h2), __half_as_ushort(h3));
  *(ushort4*)(L+idx) = make_ushort4(__half_as_ushort(l0), __half_as_ushort(l1),
                                    __half_as_ushort(l2), __half_as_ushort(l3));
}

__device__ __forceinline__ void hsplit_store2(h16* H, h16* L, size_t idx, float a, float b){
  h16 h0=__float2half(a), h1=__float2half(b);
  h16 l0=__float2half(a-__half2float(h0));
  h16 l1=__float2half(b-__half2float(h1));
  *(ushort2*)(H+idx) = make_ushort2(__half_as_ushort(h0), __half_as_ushort(h1));
  *(ushort2*)(L+idx) = make_ushort2(__half_as_ushort(l0), __half_as_ushort(l1));
}

__device__ __forceinline__ void cpasync16(uint32_t dst, const void* src){
  asm volatile("cp.async.cg.shared.global [%0], [%1], 16;" :: "r"(dst), "l"(src));
}

__device__ __forceinline__ void ldsm4(uint32_t* r, uint32_t addr){
  asm volatile("ldmatrix.sync.aligned.m8n8.x4.shared.b16 {%0,%1,%2,%3}, [%4];"
    : "=r"(r[0]),"=r"(r[1]),"=r"(r[2]),"=r"(r[3]) : "r"(addr));
}

__device__ __forceinline__ void mma16816(float* d, const uint32_t* a, const uint32_t* b){
  asm volatile("mma.sync.aligned.m16n8k16.row.col.f32.f16.f16.f32 "
    "{%0,%1,%2,%3},{%4,%5,%6,%7},{%8,%9},{%0,%1,%2,%3};"
    : "+f"(d[0]),"+f"(d[1]),"+f"(d[2]),"+f"(d[3])
    : "r"(a[0]),"r"(a[1]),"r"(a[2]),"r"(a[3]), "r"(b[0]),"r"(b[1]));
}

// swizzled byte offset within an 8KB tile (128 rows x 32 halves; 2 rows per 128B physrow)
__device__ __forceinline__ uint32_t swoff(int row, int c){
  int pr = row >> 1;
  int ch = ((row & 1)*4 + c) ^ (pr & 7);
  return (uint32_t)(pr*128 + ch*16);
}

// ---------------- operand selectors ----------------
// A: 0=x0, 1=x1, 2=msg[0], 3=msg[1], 4=cat0, 5=cat1, 6=t[0], 7=t[1]
__device__ __forceinline__ void apair(int s, const h16*& h, const h16*& l){
  switch(s){
    case 0: h=s_xh0;    l=s_xl0;    break;
    case 1: h=s_xh1;    l=s_xl1;    break;
    case 2: h=s_mh[0];  l=s_ml[0];  break;
    case 3: h=s_mh[1];  l=s_ml[1];  break;
    case 4: h=s_ch0;    l=s_cl0;    break;
    case 5: h=s_ch1;    l=s_cl1;    break;
    case 6: h=s_th[0];  l=s_tl[0];  break;
    default:h=s_th[1];  l=s_tl[1];  break;
  }
}
// B: 0 = Q rows of w_qkv, 3 = w_m, 4 = w_1, 5 = w_2
__device__ __forceinline__ const h16* bsel(int s, int layer){
  switch(s){
    case 0: return w_qkv + (size_t)layer*NQKV*CC;
    case 3: return w_m + (size_t)layer*CC*CC;
    case 4: return w_1 + (size_t)layer*C2*C2;
    default:return w_2 + (size_t)layer*CC*C2;
  }
}
// C: slot = s>>2, kind = s&3: 0=q,1=k,2=v,3=m
__device__ __forceinline__ float* cbuf(int s){
  int slot = s >> 2;
  switch(s & 3){
    case 0: return g_q[slot]; case 1: return g_k[slot];
    case 2: return g_v[slot]; default: return g_m[slot];
  }
}

// ---------------- split-fp16 GEMM via mma.sync ----------------
// CTA 128x128x32, warp 64x32, 4-stage cp.async pipeline.
#define NSTG 4
#define STG_BYTES 24576
#define MMA_SMEM (NSTG*STG_BYTES)

// Shared mainloop: accumulates into acc, given global srcs
#define GEMM_CORE(gsrcAh, gsrcAl, gsrcB, Kc)                                         \
  const int lr0 = t >> 2, lc0 = t & 3;                                               \
  const int lm = lane >> 3, lrr = lane & 7;                                          \
  const h16* gsrc[3] = { gsrcAh, gsrcAl, gsrcB };                                    \
  float acc[4][4][4];                                                                \
  _Pragma("unroll") for (int i=0;i<4;i++)                                            \
  _Pragma("unroll") for (int j=0;j<4;j++)                                            \
  _Pragma("unroll") for (int q=0;q<4;q++) acc[i][j][q] = 0.f;                        \
  const int nc = (Kc) >> 5;                                                          \
  LOAD_STAGE(0, 0); LOAD_STAGE(1, 1); LOAD_STAGE(2, 2);                              \
  for (int c = 0; c < nc; c++){                                                      \
    if (c + 3 < nc) LOAD_STAGE((c+3)%NSTG, c+3);                                     \
    int rem = nc - 1 - c;                                                            \
    if (rem >= 3)      asm volatile("cp.async.wait_group 3;" ::: "memory");          \
    else if (rem == 2) asm volatile("cp.async.wait_group 2;" ::: "memory");          \
    else if (rem == 1) asm volatile("cp.async.wait_group 1;" ::: "memory");          \
    else               asm volatile("cp.async.wait_group 0;" ::: "memory");          \
    __syncthreads();                                                                 \
    const uint32_t base = sb + (c%NSTG)*STG_BYTES;                                   \
    _Pragma("unroll")                                                                \
    for (int k16 = 0; k16 < 2; k16++){                                               \
      uint32_t ah[4][4], al[4][4], bh[4][2];                                         \
      _Pragma("unroll")                                                              \
      for (int mt = 0; mt < 4; mt++){                                                \
        int row = wm*64 + mt*16 + (lm&1)*8 + lrr;                                    \
        int ch  = k16*2 + (lm>>1);                                                   \
        uint32_t o = swoff(row, ch);                                                 \
        ldsm4(ah[mt], base + o);                                                     \
        ldsm4(al[mt], base + 8192 + o);                                              \
      }                                                                              \
      _Pragma("unroll")                                                              \
      for (int g = 0; g < 2; g++){                                                   \
        int row = wn*32 + g*16 + (lm>>1)*8 + lrr;                                    \
        int ch  = k16*2 + (lm&1);                                                    \
        uint32_t o = swoff(row, ch);                                                 \
        uint32_t r4[4];                                                              \
        ldsm4(r4, base + 16384 + o);                                                 \
        bh[g*2][0]=r4[0]; bh[g*2][1]=r4[1]; bh[g*2+1][0]=r4[2]; bh[g*2+1][1]=r4[3];  \
      }                                                                              \
      _Pragma("unroll")                                                              \
      for (int mt = 0; mt < 4; mt++)                                                 \
      _Pragma("unroll")                                                              \
        for (int nt = 0; nt < 4; nt++){                                              \
          mma16816(acc[mt][nt], ah[mt], bh[nt]);                                     \
          mma16816(acc[mt][nt], al[mt], bh[nt]);                                     \
        }                                                                            \
    }                                                                                \
    __syncthreads();                                                                 \
  }

#define LOAD_STAGE(stg, ck) do {                                              \
    uint32_t base_ = sb + (stg)*STG_BYTES;                                    \
    int k0_ = (ck)*32;                                                        \
    _Pragma("unroll")                                                         \
    for (int tl_=0; tl_<3; tl_++){                                            \
      uint32_t tb_ = base_ + tl_*8192;                                        \
      const char* g_ = (const char*)(gsrc[tl_] + k0_);                        \
      cpasync16(tb_ + swoff(lr0,    lc0), g_ + ((size_t)lr0   *K + lc0*8)*2); \
      cpasync16(tb_ + swoff(lr0+64, lc0), g_ + ((size_t)(lr0+64)*K + lc0*8)*2);\
    }                                                                         \
    asm volatile("cp.async.commit_group;");                                   \
  } while(0)

// Generic GEMM: C[M,Nw] = epi( A @ B^T ). grid (Nw/128, M/128, nz).
// EPI: 0 none->fp32, 1 elu+1->fp32, 3 relu->fp16 hi/lo into t[Csel]
template<int EPI>
__global__ __launch_bounds__(256)
void mma_gemm(int a0, int a1, int Bsel, int layer, int c0, int c1, int Nw, int K)
{
  extern __shared__ char smc[];
  const uint32_t sb = s2u(smc);
  const int z = blockIdx.z;
  const int Asel = z ? a1 : a0;
  const int Csel = z ? c1 : c0;

  const h16 *Ah,*Al;
  apair(Asel, Ah, Al);
  const h16* Bh = bsel(Bsel, layer);

  const int t = threadIdx.x, lane = t & 31, wid = t >> 5;
  const int wm = wid & 1, wn = wid >> 1;
  const int bm = blockIdx.y*128, bn = blockIdx.x*128;

  GEMM_CORE(Ah + (size_t)bm*K, Al + (size_t)bm*K, Bh + (size_t)bn*K, K)

  const int er = bm + wm*64 + (lane>>2);
  const int ec = bn + wn*32 + 2*(lane&3);
#pragma unroll
  for (int mt = 0; mt < 4; mt++){
#pragma unroll
    for (int nt = 0; nt < 4; nt++){
      int row = er + mt*16;
      int col = ec + nt*8;
      float v0 = acc[mt][nt][0], v1 = acc[mt][nt][1];
      float v2 = acc[mt][nt][2], v3 = acc[mt][nt][3];
      if (EPI == 1){
        v0 = v0 > 0.f ? v0 + 1.f : expf(v0);
        v1 = v1 > 0.f ? v1 + 1.f : expf(v1);
        v2 = v2 > 0.f ? v2 + 1.f : expf(v2);
        v3 = v3 > 0.f ? v3 + 1.f : expf(v3);
      } else if (EPI == 3){
        v0 = v0 > 0.f ? v0 : 0.f; v1 = v1 > 0.f ? v1 : 0.f;
        v2 = v2 > 0.f ? v2 : 0.f; v3 = v3 > 0.f ? v3 : 0.f;
      }
      if (EPI == 3){
        h16* TH = s_th[Csel]; h16* TL = s_tl[Csel];
        hsplit_store2(TH, TL, (size_t)row*Nw + col, v0, v1);
        hsplit_store2(TH, TL, (size_t)(row+8)*Nw + col, v2, v3);
      } else {
        float* C = cbuf(Csel);
        *(float2*)(C + (size_t)row*Nw + col)     = make_float2(v0, v1);
        *(float2*)(C + (size_t)(row+8)*Nw + col) = make_float2(v2, v3);
      }
    }
  }
}

// Fused QKV/KV GEMM: B rows come from w_qkv at rowoff + bn. Column segment
// selects epilogue (kind 0,1 -> elu+1; kind 2 -> none) and output buffer.
// grid (nseg*4, 128, nz); z selects (a0,slot0)/(a1,slot1).
__global__ __launch_bounds__(256)
void mma_gemm_qkv(int a0, int a1, int layer, int slot0, int slot1, int rowoff)
{
  extern __shared__ char smc[];
  const uint32_t sb = s2u(smc);
  const int z = blockIdx.z;
  const int Asel = z ? a1 : a0;
  const int slot = z ? slot1 : slot0;
  const int K = CC;

  const h16 *Ah,*Al;
  apair(Asel, Ah, Al);
  const int grow = rowoff + blockIdx.x*128;       // global N row in w_qkv
  const int kind = grow >> 9;                     // 0=q,1=k,2=v
  const int cbase = grow & 511;
  const h16* Bh = w_qkv + (size_t)layer*NQKV*CC + (size_t)grow*CC;

  const int t = threadIdx.x, lane = t & 31, wid = t >> 5;
  const int wm = wid & 1, wn = wid >> 1;
  const int bm = blockIdx.y*128;

  GEMM_CORE(Ah + (size_t)bm*K, Al + (size_t)bm*K, Bh, K)

  float* C = cbuf(slot*4 + kind);
  const bool do_elu = (kind < 2);
  const int er = bm + wm*64 + (lane>>2);
  const int ec = cbase + wn*32 + 2*(lane&3);
#pragma unroll
  for (int mt = 0; mt < 4; mt++){
#pragma unroll
    for (int nt = 0; nt < 4; nt++){
      int row = er + mt*16;
      int col = ec + nt*8;
      float v0 = acc[mt][nt][0], v1 = acc[mt][nt][1];
      float v2 = acc[mt][nt][2], v3 = acc[mt][nt][3];
      if (do_elu){
        v0 = v0 > 0.f ? v0 + 1.f : expf(v0);
        v1 = v1 > 0.f ? v1 + 1.f : expf(v1);
        v2 = v2 > 0.f ? v2 + 1.f : expf(v2);
        v3 = v3 > 0.f ? v3 + 1.f : expf(v3);
      }
      *(float2*)(C + (size_t)row*CC + col)     = make_float2(v0, v1);
      *(float2*)(C + (size_t)(row+8)*CC + col) = make_float2(v2, v3);
    }
  }
}

// ---------------- weight prep: one launch, transpose + fp16 ----------------
// tiles: types 0-3 (q,k,v,m): 12L x 16x16; type 4 (w1): 12L x 32x32; type 5 (w2): 12L x 16n x 32k
__global__ __launch_bounds__(256)
void wprep_all(const float* __restrict__ Wq, const float* __restrict__ Wk,
               const float* __restrict__ Wv, const float* __restrict__ Wm,
               const float* __restrict__ W1, const float* __restrict__ W2)
{
  int id = blockIdx.x;
  int type, l, n0, k0, K, N;
  const float* src;
  h16* dst; size_t dstride;
  if (id < 12288){                 // q,k,v,m
    type = id / 3072; id %= 3072;
    l = id / 256; id %= 256;
    n0 = (id / 16) * 32; k0 = (id % 16) * 32;
    K = CC; N = CC;
    switch(type){
      case 0: src=Wq; dst=w_qkv + (size_t)l*NQKV*CC;                 break;
      case 1: src=Wk; dst=w_qkv + (size_t)l*NQKV*CC + (size_t)512*CC; break;
      case 2: src=Wv; dst=w_qkv + (size_t)l*NQKV*CC + (size_t)1024*CC;break;
      default:src=Wm; dst=w_m  + (size_t)l*CC*CC;                    break;
    }
    src += (size_t)l*CC*CC;
    dstride = CC;
  } else if (id < 24576){          // w1
    id -= 12288;
    l = id / 1024; id %= 1024;
    n0 = (id / 32) * 32; k0 = (id % 32) * 32;
    K = C2; N = C2;
    src = W1 + (size_t)l*C2*C2;
    dst = w_1 + (size_t)l*C2*C2;
    dstride = C2;
  } else {                         // w2
    id -= 24576;
    l = id / 512; id %= 512;
    n0 = (id / 32) * 32; k0 = (id % 32) * 32;
    K = C2; N = CC;
    src = W2 + (size_t)l*C2*CC;
    dst = w_2 + (size_t)l*CC*C2;
    dstride = C2;
  }
  __shared__ float tile[32][33];
  const int tx = threadIdx.x & 31, ty = threadIdx.x >> 5;
#pragma unroll
  for (int i = 0; i < 4; i++){
    int r = ty + i*8;
    tile[r][tx] = src[(size_t)(k0+r)*N + n0 + tx];
  }
  __syncthreads();
#pragma unroll
  for (int i = 0; i < 4; i++){
    int r = ty + i*8;
    dst[(size_t)(n0+r)*dstride + k0 + tx] = __float2half(tile[tx][r]);
  }
}

// ---------------- attention: KV split-K (deterministic) ----------------
__global__ __launch_bounds__(256)
void kv_partial(int s0, int s1)
{
  const int slot = blockIdx.z ? s1 : s0;
  const int nh = blockIdx.y, part = blockIdx.x;
  const int n = nh >> 3, h = nh & 7;
  __shared__ float Ks[32][68];
  __shared__ float Vs[32][68];
  const int t = threadIdx.x;
  const int tx = t & 15, ty = t >> 4;
  const float* Kb = g_k[slot] + (size_t)n*LSEQ*CC + h*DD;
  const float* Vb = g_v[slot] + (size_t)n*LSEQ*CC + h*DD;
  float acc[4][4] = {};
  float ksum = 0.f;
  const int send = part*SCHUNK + SCHUNK;
  for (int s0i = part*SCHUNK; s0i < send; s0i += 32){
#pragma unroll
    for (int p = 0; p < 2; p++){
      int idx = t + p*256;
      int r = idx >> 4, c4 = (idx & 15) << 2;
      *(float4*)&Ks[r][c4] = *(const float4*)(Kb + (size_t)(s0i+r)*CC + c4);
      *(float4*)&Vs[r][c4] = *(const float4*)(Vb + (size_t)(s0i+r)*CC + c4);
    }
    __syncthreads();
    if (t < DD){
#pragma unroll
      for (int kk = 0; kk < 32; kk++) ksum += Ks[kk][t];
    }
#pragma unroll
    for (int kk = 0; kk < 32; kk++){
      float4 a = *(const float4*)&Ks[kk][ty*4];
      float4 b = *(const float4*)&Vs[kk][tx*4];
      float ar[4]={a.x,a.y,a.z,a.w}, br[4]={b.x,b.y,b.z,b.w};
#pragma unroll
      for (int i=0;i<4;i++)
#pragma unroll
        for (int j=0;j<4;j++) acc[i][j] = fmaf(ar[i],br[j],acc[i][j]);
    }
    __syncthreads();
  }
  float* dst = g_kvp[slot] + ((size_t)part*NB*HH + nh)*DD*DD;
#pragma unroll
  for (int i=0;i<4;i++)
    *(float4*)&dst[(ty*4+i)*DD + tx*4] =
        make_float4(acc[i][0],acc[i][1],acc[i][2],acc[i][3]);
  if (t < DD) g_ksp[slot][(size_t)part*NB*HH*DD + nh*DD + t] = ksum;
}

__global__ __launch_bounds__(256)
void kv_reduce(int s0, int s1)
{
  const int slot = blockIdx.z ? s1 : s0;
  int i = blockIdx.x*256 + threadIdx.x;
  if (i < NB*HH*DD*DD){
    float s = 0.f;
#pragma unroll
    for (int p=0;p<SPLIT;p++) s += g_kvp[slot][(size_t)p*NB*HH*DD*DD + i];
    g_kv[slot][i] = s;
  }
  if (i < NB*HH*DD){
    float s=0.f;
#pragma unroll
    for (int p=0;p<SPLIT;p++) s += g_ksp[slot][p*NB*HH*DD + i];
    g_ksum[slot][i] = s;
  }
}

// msg = (Q @ KVu) / (Q.Ksum+eps)  -> fp16 hi/lo pair
__global__ __launch_bounds__(256)
void msg_kernel(int s0, int s1)
{
  const int slot = blockIdx.z ? s1 : s0;
  const int nh = blockIdx.y;
  const int n = nh >> 3, h = nh & 7;
  const int l0 = blockIdx.x * 64;
  __shared__ float Qs[64][68];
  __shared__ float KVs[64][68];
  __shared__ float ksm[64];
  __shared__ float zrow[64];
  const int t = threadIdx.x;
  const int tx = t & 15, ty = t >> 4;
  const float* Qb  = g_q[slot]  + (size_t)n*LSEQ*CC + h*DD;
  const float* KVb = g_kv[slot] + (size_t)nh*DD*DD;
#pragma unroll
  for (int p=0;p<4;p++){
    int idx = t + p*256;
    int r = idx >> 4, c4 = (idx & 15) << 2;
    float4 q = *(const float4*)(Qb + (size_t)(l0+r)*CC + c4);
    Qs[c4+0][r]=q.x; Qs[c4+1][r]=q.y; Qs[c4+2][r]=q.z; Qs[c4+3][r]=q.w;
    *(float4*)&KVs[r][c4] = *(const float4*)(KVb + r*DD + c4);
  }
  if (t < DD) ksm[t] = g_ksum[slot][nh*DD + t];
  __syncthreads();
  if (t < DD){
    float dn = 0.f;
#pragma unroll
    for (int d=0; d<DD; d++) dn = fmaf(Qs[d][t], ksm[d], dn);
    zrow[t] = 1.0f / (dn + 1e-6f);
  }
  __syncthreads();
  float acc[4][4] = {};
#pragma unroll
  for (int kk=0; kk<DD; kk++){
    float4 a = *(const float4*)&Qs[kk][ty*4];
    float4 b = *(const float4*)&KVs[kk][tx*4];
    float ar[4]={a.x,a.y,a.z,a.w}, br[4]={b.x,b.y,b.z,b.w};
#pragma unroll
    for (int i=0;i<4;i++)
#pragma unroll
      for (int j=0;j<4;j++) acc[i][j] = fmaf(ar[i],br[j],acc[i][j]);
  }
#pragma unroll
  for (int i=0;i<4;i++){
    int m = ty*4+i;
    float zz = zrow[m];
    size_t base = ((size_t)(n*LSEQ + l0 + m))*CC + h*DD + tx*4;
    hsplit_store4(s_mh[slot], s_ml[slot], base,
                  acc[i][0]*zz, acc[i][1]*zz, acc[i][2]*zz, acc[i][3]*zz);
  }
}

// ---------------- LN kernels ----------------
__device__ __forceinline__ void ln_core(const float4& v, int t, float& mu, float& rs)
{
  float s  = v.x+v.y+v.z+v.w;
  float s2 = v.x*v.x + v.y*v.y + v.z*v.z + v.w*v.w;
  __shared__ float sh[8];
#pragma unroll
  for (int o=16;o>0;o>>=1){
    s  += __shfl_xor_sync(0xffffffffu, s, o);
    s2 += __shfl_xor_sync(0xffffffffu, s2, o);
  }
  if ((t & 31) == 0){ sh[t>>5] = s; sh[4 + (t>>5)] = s2; }
  __syncthreads();
  s  = sh[0]+sh[1]+sh[2]+sh[3];
  s2 = sh[4]+sh[5]+sh[6]+sh[7];
  mu = s * (1.0f/CC);
  float var = s2 * (1.0f/CC) - mu*mu;
  rs = rsqrtf(var + 1e-5f);
}

// LN(g_m[slot]) -> cat{xsel}[:, 512:1024] fp16 hi/lo
__global__ __launch_bounds__(128)
void ln_to_cat(int x0, int x1, int s0, int s1,
               const float* __restrict__ gamma, const float* __restrict__ beta)
{
  const int xsel = blockIdx.z ? x1 : x0;
  const int slot = blockIdx.z ? s1 : s0;
  const int row = blockIdx.x;
  const int t = threadIdx.x;
  float4 v = *(const float4*)(g_m[slot] + (size_t)row*CC + t*4);
  float mu, rs;
  ln_core(v, t, mu, rs);
  float4 g = *(const float4*)(gamma + t*4);
  float4 b = *(const float4*)(beta + t*4);
  float o0 = (v.x-mu)*rs*g.x + b.x;
  float o1 = (v.y-mu)*rs*g.y + b.y;
  float o2 = (v.z-mu)*rs*g.z + b.z;
  float o3 = (v.w-mu)*rs*g.w + b.w;
  h16* ch = xsel ? s_ch1 : s_ch0;
  h16* cl = xsel ? s_cl1 : s_cl0;
  hsplit_store4(ch, cl, (size_t)row*C2 + CC + t*4, o0, o1, o2, o3);
}

// x = x + LN(g_k[slot]); writes fp32 x, fp16 shadow, and cat x-half
__global__ __launch_bounds__(128)
void ln_res(int x0, int x1, int s0, int s1,
            const float* __restrict__ gamma, const float* __restrict__ beta)
{
  const int xsel = blockIdx.z ? x1 : x0;
  const int slot = blockIdx.z ? s1 : s0;
  const int row = blockIdx.x;
  const int t = threadIdx.x;
  float4 v = *(const float4*)(g_k[slot] + (size_t)row*CC + t*4);
  float mu, rs;
  ln_core(v, t, mu, rs);
  float4 g = *(const float4*)(gamma + t*4);
  float4 b = *(const float4*)(beta + t*4);
  float* x = xsel ? g_f1 : g_f0;
  h16* xh = xsel ? s_xh1 : s_xh0;
  h16* xl = xsel ? s_xl1 : s_xl0;
  h16* ch = xsel ? s_ch1 : s_ch0;
  h16* cl = xsel ? s_cl1 : s_cl0;
  float4 r = *(const float4*)(x + (size_t)row*CC + t*4);
  float o0 = (v.x-mu)*rs*g.x + b.x + r.x;
  float o1 = (v.y-mu)*rs*g.y + b.y + r.y;
  float o2 = (v.z-mu)*rs*g.z + b.z + r.z;
  float o3 = (v.w-mu)*rs*g.w + b.w + r.w;
  *(float4*)(x + (size_t)row*CC + t*4) = make_float4(o0,o1,o2,o3);
  hsplit_store4(xh, xl, (size_t)row*CC + t*4, o0, o1, o2, o3);
  hsplit_store4(ch, cl, (size_t)row*C2 + t*4, o0, o1, o2, o3);
}

__global__ __launch_bounds__(256)
void copy_in(const float* __restrict__ f0, const float* __restrict__ f1)
{
  size_t i = (size_t)blockIdx.x*256 + threadIdx.x;
  float4 a = ((const float4*)f0)[i];
  float4 b = ((const float4*)f1)[i];
  ((float4*)g_f0)[i] = a;
  ((float4*)g_f1)[i] = b;
  size_t row = i >> 7, c4 = i & 127;
  hsplit_store4(s_xh0, s_xl0, i*4, a.x, a.y, a.z, a.w);
  hsplit_store4(s_xh1, s_xl1, i*4, b.x, b.y, b.z, b.w);
  hsplit_store4(s_ch0, s_cl0, row*C2 + c4*4, a.x, a.y, a.z, a.w);
  hsplit_store4(s_ch1, s_cl1, row*C2 + c4*4, b.x, b.y, b.z, b.w);
}

__global__ __launch_bounds__(256)
void copy_out(float* __restrict__ out)
{
  size_t i = (size_t)blockIdx.x*256 + threadIdx.x;
  ((float4*)out)[i]          = ((const float4*)g_f0)[i];
  ((float4*)out)[i + ELEMS4] = ((const float4*)g_f1)[i];
}

// ---------------- host-side layer drivers ----------------
static void enc_dual(int layer,
                     const float* gg1, const float* bb1,
                     const float* gg2, const float* bb2)
{
  dim3 blk(256);
  dim3 gq(4, 128, 2);
  dim3 g1k(8, 128, 2);
  mma_gemm_qkv<<<dim3(12,128,2), blk, MMA_SMEM>>>(0, 1, layer, 0, 1, 0);   // QKV fused
  kv_partial<<<dim3(SPLIT, NB*HH, 2), blk>>>(0, 1);
  kv_reduce<<<dim3(512, 1, 2), blk>>>(0, 1);
  msg_kernel<<<dim3(LSEQ/64, NB*HH, 2), blk>>>(0, 1);
  mma_gemm<0><<<gq,  blk, MMA_SMEM>>>(2, 3, 3, layer, 3, 7, CC, CC);       // msg@Wm -> m
  ln_to_cat<<<dim3(ROWS,1,2), 128>>>(0, 1, 0, 1, gg1, bb1);
  mma_gemm<3><<<g1k, blk, MMA_SMEM>>>(4, 5, 4, layer, 0, 1, C2, C2);       // relu(cat@W1) -> t[slot]
  mma_gemm<0><<<gq,  blk, MMA_SMEM>>>(6, 7, 5, layer, 1, 5, CC, C2);       // t@W2 -> k[slot]
  ln_res<<<dim3(ROWS,1,2), 128>>>(0, 1, 0, 1, gg2, bb2);
}

static void enc_single(int xsel, int ssel, int layer,
                       const float* gg1, const float* bb1,
                       const float* gg2, const float* bb2)
{
  dim3 blk(256);
  dim3 gq(4, 128, 1);
  dim3 g1k(8, 128, 1);
  mma_gemm<1><<<gq, blk, MMA_SMEM>>>(xsel, 0, 0, layer, 0, 0, CC, CC);     // Q -> q[0]
  mma_gemm_qkv<<<dim3(8,128,1), blk, MMA_SMEM>>>(ssel, 0, layer, 0, 0, 512); // K,V fused
  kv_partial<<<dim3(SPLIT, NB*HH, 1), blk>>>(0, 0);
  kv_reduce<<<dim3(512, 1, 1), blk>>>(0, 0);
  msg_kernel<<<dim3(LSEQ/64, NB*HH, 1), blk>>>(0, 0);
  mma_gemm<0><<<gq,  blk, MMA_SMEM>>>(2, 0, 3, layer, 3, 0, CC, CC);       // msg@Wm -> m[0]
  ln_to_cat<<<dim3(ROWS,1,1), 128>>>(xsel, 0, 0, 0, gg1, bb1);
  mma_gemm<3><<<g1k, blk, MMA_SMEM>>>(4+xsel, 0, 4, layer, 0, 0, C2, C2);  // -> t[0]
  mma_gemm<0><<<gq,  blk, MMA_SMEM>>>(6, 0, 5, layer, 1, 0, CC, C2);       // -> k[0]
  ln_res<<<dim3(ROWS,1,1), 128>>>(xsel, 0, 0, 0, gg2, bb2);
}

extern "C" void kernel_launch(void* const* d_in, const int* in_sizes, int n_in,
                              void* d_out, int out_size)
{
  (void)in_sizes; (void)n_in; (void)out_size;
  const float* feat0 = (const float*)d_in[0];
  const float* feat1 = (const float*)d_in[1];
  const float* Wq = (const float*)d_in[2];
  const float* Wk = (const float*)d_in[3];
  const float* Wv = (const float*)d_in[4];
  const float* Wm = (const float*)d_in[5];
  const float* W1 = (const float*)d_in[6];
  const float* W2 = (const float*)d_in[7];
  const float* g1 = (const float*)d_in[8];
  const float* b1 = (const float*)d_in[9];
  const float* g2 = (const float*)d_in[10];
  const float* b2 = (const float*)d_in[11];

  cudaFuncSetAttribute(mma_gemm<0>, cudaFuncAttributeMaxDynamicSharedMemorySize, MMA_SMEM);
  cudaFuncSetAttribute(mma_gemm<1>, cudaFuncAttributeMaxDynamicSharedMemorySize, MMA_SMEM);
  cudaFuncSetAttribute(mma_gemm<3>, cudaFuncAttributeMaxDynamicSharedMemorySize, MMA_SMEM);
  cudaFuncSetAttribute(mma_gemm_qkv, cudaFuncAttributeMaxDynamicSharedMemorySize, MMA_SMEM);

  wprep_all<<<30720, 256>>>(Wq, Wk, Wv, Wm, W1, W2);
  copy_in<<<ELEMS4/256, 256>>>(feat0, feat1);

  for (int i = 0; i < NLAYERS; i++){
    const float* gg1 = g1 + (size_t)i*CC;
    const float* bb1 = b1 + (size_t)i*CC;
    const float* gg2 = g2 + (size_t)i*CC;
    const float* bb2 = b2 + (size_t)i*CC;
    if ((i & 1) == 0){  // self: feat0 and feat1 independent, same weights
      enc_dual(i, gg1, bb1, gg2, bb2);
    } else {            // cross (sequential: feat1 sees updated feat0)
      enc_single(0, 1, i, gg1, bb1, gg2, bb2);
      enc_single(1, 0, i, gg1, bb1, gg2, bb2);
    }
  }

  copy_out<<<ELEMS4/256, 256>>>((float*)d_out);
}

// round 15
// speedup vs baseline: 1.1578x; 1.0052x over previous
#include <cuda_runtime.h>
#include <cuda_fp16.h>
#include <math.h>
#include <stdint.h>

#define NB 4
#define LSEQ 4096
#define CC 512
#define C2 1024
#define HH 8
#define DD 64
#define ROWS (NB*LSEQ)          // 16384
#define SPLIT 32
#define SCHUNK (LSEQ/SPLIT)     // 128
#define NLAYERS 12
#define ELEMS (ROWS*CC)         // 8388608
#define ELEMS4 (ELEMS/4)
#define NQKV 1536

typedef __half h16;

// ---------------- device globals (no allocation) ----------------
__device__ float g_f0[ELEMS], g_f1[ELEMS];
__device__ float g_q[2][ELEMS], g_k[2][ELEMS], g_v[2][ELEMS], g_m[2][ELEMS];
__device__ float g_kvp[2][SPLIT*NB*HH*DD*DD];
__device__ float g_ksp[2][SPLIT*NB*HH*DD];
__device__ float g_kv[2][NB*HH*DD*DD];
__device__ float g_ksum[2][NB*HH*DD];

// fp16 hi/lo activation shadows
__device__ h16 s_xh0[ELEMS], s_xl0[ELEMS], s_xh1[ELEMS], s_xl1[ELEMS];
__device__ h16 s_mh[2][ELEMS], s_ml[2][ELEMS];
__device__ h16 s_ch0[ROWS*C2], s_cl0[ROWS*C2];
__device__ h16 s_ch1[ROWS*C2], s_cl1[ROWS*C2];
__device__ h16 s_th[2][ROWS*C2], s_tl[2][ROWS*C2];

// transposed fp16 weights: [N rows][K cols], per layer
__device__ h16 w_qkv[NLAYERS*NQKV*CC];   // rows 0-511 Wq, 512-1023 Wk, 1024-1535 Wv
__device__ h16 w_m[NLAYERS*CC*CC];
__device__ h16 w_1[NLAYERS*C2*C2];
__device__ h16 w_2[NLAYERS*CC*C2];

// ---------------- helpers ----------------
__device__ __forceinline__ uint32_t s2u(const void* p){
  uint32_t a;
  asm("{ .reg .u64 t; cvta.to.shared.u64 t, %1; cvt.u32.u64 %0, t; }" : "=r"(a) : "l"(p));
  return a;
}

__device__ __forceinline__ void hsplit_store4(h16* H, h16* L, size_t idx,
                                              float a, float b, float c, float d){
  h16 h0=__float2half(a), h1=__float2half(b), h2=__float2half(c), h3=__float2half(d);
  h16 l0=__float2half(a-__half2float(h0));
  h16 l1=__float2half(b-__half2float(h1));
  h16 l2=__float2half(c-__half2float(h2));
  h16 l3=__float2half(d-__half2float(h3));
  *(ushort4*)(H+idx) = make_ushort4(__half_as_ushort(h0), __half_as_ushort(h1),
                                    __half_as_ushort(h2), __half_as_ushort(h3));
  *(ushort4*)(L+idx) = make_ushort4(__half_as_ushort(l0), __half_as_ushort(l1),
                                    __half_as_ushort(l2), __half_as_ushort(l3));
}

__device__ __forceinline__ void hsplit_store2(h16* H, h16* L, size_t idx, float a, float b){
  h16 h0=__float2half(a), h1=__float2half(b);
  h16 l0=__float2half(a-__half2float(h0));
  h16 l1=__float2half(b-__half2float(h1));
  *(ushort2*)(H+idx) = make_ushort2(__half_as_ushort(h0), __half_as_ushort(h1));
  *(ushort2*)(L+idx) = make_ushort2(__half_as_ushort(l0), __half_as_ushort(l1));
}

__device__ __forceinline__ void cpasync16(uint32_t dst, const void* src){
  asm volatile("cp.async.cg.shared.global [%0], [%1], 16;" :: "r"(dst), "l"(src));
}

__device__ __forceinline__ void ldsm4(uint32_t* r, uint32_t addr){
  asm volatile("ldmatrix.sync.aligned.m8n8.x4.shared.b16 {%0,%1,%2,%3}, [%4];"
    : "=r"(r[0]),"=r"(r[1]),"=r"(r[2]),"=r"(r[3]) : "r"(addr));
}

__device__ __forceinline__ void mma16816(float* d, const uint32_t* a, const uint32_t* b){
  asm volatile("mma.sync.aligned.m16n8k16.row.col.f32.f16.f16.f32 "
    "{%0,%1,%2,%3},{%4,%5,%6,%7},{%8,%9},{%0,%1,%2,%3};"
    : "+f"(d[0]),"+f"(d[1]),"+f"(d[2]),"+f"(d[3])
    : "r"(a[0]),"r"(a[1]),"r"(a[2]),"r"(a[3]), "r"(b[0]),"r"(b[1]));
}

// swizzled byte offset within a tile (rows x 32 halves; 2 rows per 128B physrow)
__device__ __forceinline__ uint32_t swoff(int row, int c){
  int pr = row >> 1;
  int ch = ((row & 1)*4 + c) ^ (pr & 7);
  return (uint32_t)(pr*128 + ch*16);
}

// ---------------- operand selectors ----------------
// A: 0=x0, 1=x1, 2=msg[0], 3=msg[1], 4=cat0, 5=cat1, 6=t[0], 7=t[1]
__device__ __forceinline__ void apair(int s, const h16*& h, const h16*& l){
  switch(s){
    case 0: h=s_xh0;    l=s_xl0;    break;
    case 1: h=s_xh1;    l=s_xl1;    break;
    case 2: h=s_mh[0];  l=s_ml[0];  break;
    case 3: h=s_mh[1];  l=s_ml[1];  break;
    case 4: h=s_ch0;    l=s_cl0;    break;
    case 5: h=s_ch1;    l=s_cl1;    break;
    case 6: h=s_th[0];  l=s_tl[0];  break;
    default:h=s_th[1];  l=s_tl[1];  break;
  }
}
// B: 0 = Q rows of w_qkv, 3 = w_m, 4 = w_1, 5 = w_2
__device__ __forceinline__ const h16* bsel(int s, int layer){
  switch(s){
    case 0: return w_qkv + (size_t)layer*NQKV*CC;
    case 3: return w_m + (size_t)layer*CC*CC;
    case 4: return w_1 + (size_t)layer*C2*C2;
    default:return w_2 + (size_t)layer*CC*C2;
  }
}
// C: slot = s>>2, kind = s&3: 0=q,1=k,2=v,3=m
__device__ __forceinline__ float* cbuf(int s){
  int slot = s >> 2;
  switch(s & 3){
    case 0: return g_q[slot]; case 1: return g_k[slot];
    case 2: return g_v[slot]; default: return g_m[slot];
  }
}

// ---------------- split-fp16 GEMM via mma.sync ----------------
// CTA 128x128x32, warp 64x32, 4-stage cp.async pipeline.
#define NSTG 4
#define STG_BYTES 24576
#define MMA_SMEM (NSTG*STG_BYTES)

// Shared mainloop: accumulates into acc, given global srcs
#define GEMM_CORE(gsrcAh, gsrcAl, gsrcB, Kc)                                         \
  const int lr0 = t >> 2, lc0 = t & 3;                                               \
  const int lm = lane >> 3, lrr = lane & 7;                                          \
  const h16* gsrc[3] = { gsrcAh, gsrcAl, gsrcB };                                    \
  float acc[4][4][4];                                                                \
  _Pragma("unroll") for (int i=0;i<4;i++)                                            \
  _Pragma("unroll") for (int j=0;j<4;j++)                                            \
  _Pragma("unroll") for (int q=0;q<4;q++) acc[i][j][q] = 0.f;                        \
  const int nc = (Kc) >> 5;                                                          \
  LOAD_STAGE(0, 0); LOAD_STAGE(1, 1); LOAD_STAGE(2, 2);                              \
  for (int c = 0; c < nc; c++){                                                      \
    if (c + 3 < nc) LOAD_STAGE((c+3)%NSTG, c+3);                                     \
    int rem = nc - 1 - c;                                                            \
    if (rem >= 3)      asm volatile("cp.async.wait_group 3;" ::: "memory");          \
    else if (rem == 2) asm volatile("cp.async.wait_group 2;" ::: "memory");          \
    else if (rem == 1) asm volatile("cp.async.wait_group 1;" ::: "memory");          \
    else               asm volatile("cp.async.wait_group 0;" ::: "memory");          \
    __syncthreads();                                                                 \
    const uint32_t base = sb + (c%NSTG)*STG_BYTES;                                   \
    _Pragma("unroll")                                                                \
    for (int k16 = 0; k16 < 2; k16++){                                               \
      uint32_t ah[4][4], al[4][4], bh[4][2];                                         \
      _Pragma("unroll")                                                              \
      for (int mt = 0; mt < 4; mt++){                                                \
        int row = wm*64 + mt*16 + (lm&1)*8 + lrr;                                    \
        int ch  = k16*2 + (lm>>1);                                                   \
        uint32_t o = swoff(row, ch);                                                 \
        ldsm4(ah[mt], base + o);                                                     \
        ldsm4(al[mt], base + 8192 + o);                                              \
      }                                                                              \
      _Pragma("unroll")                                                              \
      for (int g = 0; g < 2; g++){                                                   \
        int row = wn*32 + g*16 + (lm>>1)*8 + lrr;                                    \
        int ch  = k16*2 + (lm&1);                                                    \
        uint32_t o = swoff(row, ch);                                                 \
        uint32_t r4[4];                                                              \
        ldsm4(r4, base + 16384 + o);                                                 \
        bh[g*2][0]=r4[0]; bh[g*2][1]=r4[1]; bh[g*2+1][0]=r4[2]; bh[g*2+1][1]=r4[3];  \
      }                                                                              \
      _Pragma("unroll")                                                              \
      for (int mt = 0; mt < 4; mt++)                                                 \
      _Pragma("unroll")                                                              \
        for (int nt = 0; nt < 4; nt++){                                              \
          mma16816(acc[mt][nt], ah[mt], bh[nt]);                                     \
          mma16816(acc[mt][nt], al[mt], bh[nt]);                                     \
        }                                                                            \
    }                                                                                \
    __syncthreads();                                                                 \
  }

#define LOAD_STAGE(stg, ck) do {                                              \
    uint32_t base_ = sb + (stg)*STG_BYTES;                                    \
    int k0_ = (ck)*32;                                                        \
    _Pragma("unroll")                                                         \
    for (int tl_=0; tl_<3; tl_++){                                            \
      uint32_t tb_ = base_ + tl_*8192;                                        \
      const char* g_ = (const char*)(gsrc[tl_] + k0_);                        \
      cpasync16(tb_ + swoff(lr0,    lc0), g_ + ((size_t)lr0   *K + lc0*8)*2); \
      cpasync16(tb_ + swoff(lr0+64, lc0), g_ + ((size_t)(lr0+64)*K + lc0*8)*2);\
    }                                                                         \
    asm volatile("cp.async.commit_group;");                                   \
  } while(0)

// Generic GEMM: C[M,Nw] = epi( A @ B^T ). grid (Nw/128, M/128, nz).
// EPI: 0 none->fp32, 1 elu+1->fp32, 3 relu->fp16 hi/lo into t[Csel]
template<int EPI>
__global__ __launch_bounds__(256)
void mma_gemm(int a0, int a1, int Bsel, int layer, int c0, int c1, int Nw, int K)
{
  extern __shared__ char smc[];
  const uint32_t sb = s2u(smc);
  const int z = blockIdx.z;
  const int Asel = z ? a1 : a0;
  const int Csel = z ? c1 : c0;

  const h16 *Ah,*Al;
  apair(Asel, Ah, Al);
  const h16* Bh = bsel(Bsel, layer);

  const int t = threadIdx.x, lane = t & 31, wid = t >> 5;
  const int wm = wid & 1, wn = wid >> 1;
  const int bm = blockIdx.y*128, bn = blockIdx.x*128;

  GEMM_CORE(Ah + (size_t)bm*K, Al + (size_t)bm*K, Bh + (size_t)bn*K, K)

  const int er = bm + wm*64 + (lane>>2);
  const int ec = bn + wn*32 + 2*(lane&3);
#pragma unroll
  for (int mt = 0; mt < 4; mt++){
#pragma unroll
    for (int nt = 0; nt < 4; nt++){
      int row = er + mt*16;
      int col = ec + nt*8;
      float v0 = acc[mt][nt][0], v1 = acc[mt][nt][1];
      float v2 = acc[mt][nt][2], v3 = acc[mt][nt][3];
      if (EPI == 1){
        v0 = v0 > 0.f ? v0 + 1.f : expf(v0);
        v1 = v1 > 0.f ? v1 + 1.f : expf(v1);
        v2 = v2 > 0.f ? v2 + 1.f : expf(v2);
        v3 = v3 > 0.f ? v3 + 1.f : expf(v3);
      } else if (EPI == 3){
        v0 = v0 > 0.f ? v0 : 0.f; v1 = v1 > 0.f ? v1 : 0.f;
        v2 = v2 > 0.f ? v2 : 0.f; v3 = v3 > 0.f ? v3 : 0.f;
      }
      if (EPI == 3){
        h16* TH = s_th[Csel]; h16* TL = s_tl[Csel];
        hsplit_store2(TH, TL, (size_t)row*Nw + col, v0, v1);
        hsplit_store2(TH, TL, (size_t)(row+8)*Nw + col, v2, v3);
      } else {
        float* C = cbuf(Csel);
        *(float2*)(C + (size_t)row*Nw + col)     = make_float2(v0, v1);
        *(float2*)(C + (size_t)(row+8)*Nw + col) = make_float2(v2, v3);
      }
    }
  }
}

// Fused QKV/KV GEMM: B rows come from w_qkv at rowoff + bn. Column segment
// selects epilogue (kind 0,1 -> elu+1; kind 2 -> none) and output buffer.
// grid (nseg, 128, nz); z selects (a0,slot0)/(a1,slot1).
__global__ __launch_bounds__(256)
void mma_gemm_qkv(int a0, int a1, int layer, int slot0, int slot1, int rowoff)
{
  extern __shared__ char smc[];
  const uint32_t sb = s2u(smc);
  const int z = blockIdx.z;
  const int Asel = z ? a1 : a0;
  const int slot = z ? slot1 : slot0;
  const int K = CC;

  const h16 *Ah,*Al;
  apair(Asel, Ah, Al);
  const int grow = rowoff + blockIdx.x*128;       // global N row in w_qkv
  const int kind = grow >> 9;                     // 0=q,1=k,2=v
  const int cbase = grow & 511;
  const h16* Bh = w_qkv + (size_t)layer*NQKV*CC + (size_t)grow*CC;

  const int t = threadIdx.x, lane = t & 31, wid = t >> 5;
  const int wm = wid & 1, wn = wid >> 1;
  const int bm = blockIdx.y*128;

  GEMM_CORE(Ah + (size_t)bm*K, Al + (size_t)bm*K, Bh, K)

  float* C = cbuf(slot*4 + kind);
  const bool do_elu = (kind < 2);
  const int er = bm + wm*64 + (lane>>2);
  const int ec = cbase + wn*32 + 2*(lane&3);
#pragma unroll
  for (int mt = 0; mt < 4; mt++){
#pragma unroll
    for (int nt = 0; nt < 4; nt++){
      int row = er + mt*16;
      int col = ec + nt*8;
      float v0 = acc[mt][nt][0], v1 = acc[mt][nt][1];
      float v2 = acc[mt][nt][2], v3 = acc[mt][nt][3];
      if (do_elu){
        v0 = v0 > 0.f ? v0 + 1.f : expf(v0);
        v1 = v1 > 0.f ? v1 + 1.f : expf(v1);
        v2 = v2 > 0.f ? v2 + 1.f : expf(v2);
        v3 = v3 > 0.f ? v3 + 1.f : expf(v3);
      }
      *(float2*)(C + (size_t)row*CC + col)     = make_float2(v0, v1);
      *(float2*)(C + (size_t)(row+8)*CC + col) = make_float2(v2, v3);
    }
  }
}

// ---------------- weight prep: one launch, transpose + fp16 ----------------
__global__ __launch_bounds__(256)
void wprep_all(const float* __restrict__ Wq, const float* __restrict__ Wk,
               const float* __restrict__ Wv, const float* __restrict__ Wm,
               const float* __restrict__ W1, const float* __restrict__ W2)
{
  int id = blockIdx.x;
  int type, l, n0, k0, K, N;
  const float* src;
  h16* dst; size_t dstride;
  if (id < 12288){                 // q,k,v,m
    type = id / 3072; id %= 3072;
    l = id / 256; id %= 256;
    n0 = (id / 16) * 32; k0 = (id % 16) * 32;
    K = CC; N = CC;
    switch(type){
      case 0: src=Wq; dst=w_qkv + (size_t)l*NQKV*CC;                 break;
      case 1: src=Wk; dst=w_qkv + (size_t)l*NQKV*CC + (size_t)512*CC; break;
      case 2: src=Wv; dst=w_qkv + (size_t)l*NQKV*CC + (size_t)1024*CC;break;
      default:src=Wm; dst=w_m  + (size_t)l*CC*CC;                    break;
    }
    src += (size_t)l*CC*CC;
    dstride = CC;
  } else if (id < 24576){          // w1
    id -= 12288;
    l = id / 1024; id %= 1024;
    n0 = (id / 32) * 32; k0 = (id % 32) * 32;
    K = C2; N = C2;
    src = W1 + (size_t)l*C2*C2;
    dst = w_1 + (size_t)l*C2*C2;
    dstride = C2;
  } else {                         // w2
    id -= 24576;
    l = id / 512; id %= 512;
    n0 = (id / 32) * 32; k0 = (id % 32) * 32;
    K = C2; N = CC;
    src = W2 + (size_t)l*C2*CC;
    dst = w_2 + (size_t)l*CC*C2;
    dstride = C2;
  }
  __shared__ float tile[32][33];
  const int tx = threadIdx.x & 31, ty = threadIdx.x >> 5;
#pragma unroll
  for (int i = 0; i < 4; i++){
    int r = ty + i*8;
    tile[r][tx] = src[(size_t)(k0+r)*N + n0 + tx];
  }
  __syncthreads();
#pragma unroll
  for (int i = 0; i < 4; i++){
    int r = ty + i*8;
    dst[(size_t)(n0+r)*dstride + k0 + tx] = __float2half(tile[tx][r]);
  }
}

// ---------------- attention: KV split-K (deterministic) ----------------
__global__ __launch_bounds__(256)
void kv_partial(int s0, int s1)
{
  const int slot = blockIdx.z ? s1 : s0;
  const int nh = blockIdx.y, part = blockIdx.x;
  const int n = nh >> 3, h = nh & 7;
  __shared__ float Ks[32][68];
  __shared__ float Vs[32][68];
  const int t = threadIdx.x;
  const int tx = t & 15, ty = t >> 4;
  const float* Kb = g_k[slot] + (size_t)n*LSEQ*CC + h*DD;
  const float* Vb = g_v[slot] + (size_t)n*LSEQ*CC + h*DD;
  float acc[4][4] = {};
  float ksum = 0.f;
  const int send = part*SCHUNK + SCHUNK;
  for (int s0i = part*SCHUNK; s0i < send; s0i += 32){
#pragma unroll
    for (int p = 0; p < 2; p++){
      int idx = t + p*256;
      int r = idx >> 4, c4 = (idx & 15) << 2;
      *(float4*)&Ks[r][c4] = *(const float4*)(Kb + (size_t)(s0i+r)*CC + c4);
      *(float4*)&Vs[r][c4] = *(const float4*)(Vb + (size_t)(s0i+r)*CC + c4);
    }
    __syncthreads();
    if (t < DD){
#pragma unroll
      for (int kk = 0; kk < 32; kk++) ksum += Ks[kk][t];
    }
#pragma unroll
    for (int kk = 0; kk < 32; kk++){
      float4 a = *(const float4*)&Ks[kk][ty*4];
      float4 b = *(const float4*)&Vs[kk][tx*4];
      float ar[4]={a.x,a.y,a.z,a.w}, br[4]={b.x,b.y,b.z,b.w};
#pragma unroll
      for (int i=0;i<4;i++)
#pragma unroll
        for (int j=0;j<4;j++) acc[i][j] = fmaf(ar[i],br[j],acc[i][j]);
    }
    __syncthreads();
  }
  float* dst = g_kvp[slot] + ((size_t)part*NB*HH + nh)*DD*DD;
#pragma unroll
  for (int i=0;i<4;i++)
    *(float4*)&dst[(ty*4+i)*DD + tx*4] =
        make_float4(acc[i][0],acc[i][1],acc[i][2],acc[i][3]);
  if (t < DD) g_ksp[slot][(size_t)part*NB*HH*DD + nh*DD + t] = ksum;
}

__global__ __launch_bounds__(256)
void kv_reduce(int s0, int s1)
{
  const int slot = blockIdx.z ? s1 : s0;
  int i = blockIdx.x*256 + threadIdx.x;
  if (i < NB*HH*DD*DD){
    float s = 0.f;
#pragma unroll
    for (int p=0;p<SPLIT;p++) s += g_kvp[slot][(size_t)p*NB*HH*DD*DD + i];
    g_kv[slot][i] = s;
  }
  if (i < NB*HH*DD){
    float s=0.f;
#pragma unroll
    for (int p=0;p<SPLIT;p++) s += g_ksp[slot][p*NB*HH*DD + i];
    g_ksum[slot][i] = s;
  }
}

// msg = (Q @ KVu) / (Q.Ksum+eps)  -> fp16 hi/lo pair
__global__ __launch_bounds__(256)
void msg_kernel(int s0, int s1)
{
  const int slot = blockIdx.z ? s1 : s0;
  const int nh = blockIdx.y;
  const int n = nh >> 3, h = nh & 7;
  const int l0 = blockIdx.x * 64;
  __shared__ float Qs[64][68];
  __shared__ float KVs[64][68];
  __shared__ float ksm[64];
  __shared__ float zrow[64];
  const int t = threadIdx.x;
  const int tx = t & 15, ty = t >> 4;
  const float* Qb  = g_q[slot]  + (size_t)n*LSEQ*CC + h*DD;
  const float* KVb = g_kv[slot] + (size_t)nh*DD*DD;
#pragma unroll
  for (int p=0;p<4;p++){
    int idx = t + p*256;
    int r = idx >> 4, c4 = (idx & 15) << 2;
    float4 q = *(const float4*)(Qb + (size_t)(l0+r)*CC + c4);
    Qs[c4+0][r]=q.x; Qs[c4+1][r]=q.y; Qs[c4+2][r]=q.z; Qs[c4+3][r]=q.w;
    *(float4*)&KVs[r][c4] = *(const float4*)(KVb + r*DD + c4);
  }
  if (t < DD) ksm[t] = g_ksum[slot][nh*DD + t];
  __syncthreads();
  if (t < DD){
    float dn = 0.f;
#pragma unroll
    for (int d=0; d<DD; d++) dn = fmaf(Qs[d][t], ksm[d], dn);
    zrow[t] = 1.0f / (dn + 1e-6f);
  }
  __syncthreads();
  float acc[4][4] = {};
#pragma unroll
  for (int kk=0; kk<DD; kk++){
    float4 a = *(const float4*)&Qs[kk][ty*4];
    float4 b = *(const float4*)&KVs[kk][tx*4];
    float ar[4]={a.x,a.y,a.z,a.w}, br[4]={b.x,b.y,b.z,b.w};
#pragma unroll
    for (int i=0;i<4;i++)
#pragma unroll
      for (int j=0;j<4;j++) acc[i][j] = fmaf(ar[i],br[j],acc[i][j]);
  }
#pragma unroll
  for (int i=0;i<4;i++){
    int m = ty*4+i;
    float zz = zrow[m];
    size_t base = ((size_t)(n*LSEQ + l0 + m))*CC + h*DD + tx*4;
    hsplit_store4(s_mh[slot], s_ml[slot], base,
                  acc[i][0]*zz, acc[i][1]*zz, acc[i][2]*zz, acc[i][3]*zz);
  }
}

// ---------------- LN kernels ----------------
__device__ __forceinline__ void ln_core(const float4& v, int t, float& mu, float& rs)
{
  float s  = v.x+v.y+v.z+v.w;
  float s2 = v.x*v.x + v.y*v.y + v.z*v.z + v.w*v.w;
  __shared__ float sh[8];
#pragma unroll
  for (int o=16;o>0;o>>=1){
    s  += __shfl_xor_sync(0xffffffffu, s, o);
    s2 += __shfl_xor_sync(0xffffffffu, s2, o);
  }
  if ((t & 31) == 0){ sh[t>>5] = s; sh[4 + (t>>5)] = s2; }
  __syncthreads();
  s  = sh[0]+sh[1]+sh[2]+sh[3];
  s2 = sh[4]+sh[5]+sh[6]+sh[7];
  mu = s * (1.0f/CC);
  float var = s2 * (1.0f/CC) - mu*mu;
  rs = rsqrtf(var + 1e-5f);
}

// LN(g_m[slot]) -> cat{xsel}[:, 512:1024] fp16 hi/lo
__global__ __launch_bounds__(128)
void ln_to_cat(int x0, int x1, int s0, int s1,
               const float* __restrict__ gamma, const float* __restrict__ beta)
{
  const int xsel = blockIdx.z ? x1 : x0;
  const int slot = blockIdx.z ? s1 : s0;
  const int row = blockIdx.x;
  const int t = threadIdx.x;
  float4 v = *(const float4*)(g_m[slot] + (size_t)row*CC + t*4);
  float mu, rs;
  ln_core(v, t, mu, rs);
  float4 g = *(const float4*)(gamma + t*4);
  float4 b = *(const float4*)(beta + t*4);
  float o0 = (v.x-mu)*rs*g.x + b.x;
  float o1 = (v.y-mu)*rs*g.y + b.y;
  float o2 = (v.z-mu)*rs*g.z + b.z;
  float o3 = (v.w-mu)*rs*g.w + b.w;
  h16* ch = xsel ? s_ch1 : s_ch0;
  h16* cl = xsel ? s_cl1 : s_cl0;
  hsplit_store4(ch, cl, (size_t)row*C2 + CC + t*4, o0, o1, o2, o3);
}

// x = x + LN(g_k[slot]); writes fp32 x, fp16 shadow, and cat x-half
__global__ __launch_bounds__(128)
void ln_res(int x0, int x1, int s0, int s1,
            const float* __restrict__ gamma, const float* __restrict__ beta)
{
  const int xsel = blockIdx.z ? x1 : x0;
  const int slot = blockIdx.z ? s1 : s0;
  const int row = blockIdx.x;
  const int t = threadIdx.x;
  float4 v = *(const float4*)(g_k[slot] + (size_t)row*CC + t*4);
  float mu, rs;
  ln_core(v, t, mu, rs);
  float4 g = *(const float4*)(gamma + t*4);
  float4 b = *(const float4*)(beta + t*4);
  float* x = xsel ? g_f1 : g_f0;
  h16* xh = xsel ? s_xh1 : s_xh0;
  h16* xl = xsel ? s_xl1 : s_xl0;
  h16* ch = xsel ? s_ch1 : s_ch0;
  h16* cl = xsel ? s_cl1 : s_cl0;
  float4 r = *(const float4*)(x + (size_t)row*CC + t*4);
  float o0 = (v.x-mu)*rs*g.x + b.x + r.x;
  float o1 = (v.y-mu)*rs*g.y + b.y + r.y;
  float o2 = (v.z-mu)*rs*g.z + b.z + r.z;
  float o3 = (v.w-mu)*rs*g.w + b.w + r.w;
  *(float4*)(x + (size_t)row*CC + t*4) = make_float4(o0,o1,o2,o3);
  hsplit_store4(xh, xl, (size_t)row*CC + t*4, o0, o1, o2, o3);
  hsplit_store4(ch, cl, (size_t)row*C2 + t*4, o0, o1, o2, o3);
}

__global__ __launch_bounds__(256)
void copy_in(const float* __restrict__ f0, const float* __restrict__ f1)
{
  size_t i = (size_t)blockIdx.x*256 + threadIdx.x;
  float4 a = ((const float4*)f0)[i];
  float4 b = ((const float4*)f1)[i];
  ((float4*)g_f0)[i] = a;
  ((float4*)g_f1)[i] = b;
  size_t row = i >> 7, c4 = i & 127;
  hsplit_store4(s_xh0, s_xl0, i*4, a.x, a.y, a.z, a.w);
  hsplit_store4(s_xh1, s_xl1, i*4, b.x, b.y, b.z, b.w);
  hsplit_store4(s_ch0, s_cl0, row*C2 + c4*4, a.x, a.y, a.z, a.w);
  hsplit_store4(s_ch1, s_cl1, row*C2 + c4*4, b.x, b.y, b.z, b.w);
}

__global__ __launch_bounds__(256)
void copy_out(float* __restrict__ out)
{
  size_t i = (size_t)blockIdx.x*256 + threadIdx.x;
  ((float4*)out)[i]          = ((const float4*)g_f0)[i];
  ((float4*)out)[i + ELEMS4] = ((const float4*)g_f1)[i];
}

// ---------------- host-side layer drivers ----------------
static void enc_dual(int layer,
                     const float* gg1, const float* bb1,
                     const float* gg2, const float* bb2)
{
  dim3 blk(256);
  dim3 gq(4, 128, 2);
  dim3 g1k(8, 128, 2);
  mma_gemm_qkv<<<dim3(12,128,2), blk, MMA_SMEM>>>(0, 1, layer, 0, 1, 0);   // QKV fused
  kv_partial<<<dim3(SPLIT, NB*HH, 2), blk>>>(0, 1);
  kv_reduce<<<dim3(512, 1, 2), blk>>>(0, 1);
  msg_kernel<<<dim3(LSEQ/64, NB*HH, 2), blk>>>(0, 1);
  mma_gemm<0><<<gq,  blk, MMA_SMEM>>>(2, 3, 3, layer, 3, 7, CC, CC);       // msg@Wm -> m
  ln_to_cat<<<dim3(ROWS,1,2), 128>>>(0, 1, 0, 1, gg1, bb1);
  mma_gemm<3><<<g1k, blk, MMA_SMEM>>>(4, 5, 4, layer, 0, 1, C2, C2);       // relu(cat@W1) -> t[slot]
  mma_gemm<0><<<gq,  blk, MMA_SMEM>>>(6, 7, 5, layer, 1, 5, CC, C2);       // t@W2 -> k[slot]
  ln_res<<<dim3(ROWS,1,2), 128>>>(0, 1, 0, 1, gg2, bb2);
}

static void enc_single(int xsel, int ssel, int layer,
                       const float* gg1, const float* bb1,
                       const float* gg2, const float* bb2)
{
  dim3 blk(256);
  dim3 gq(4, 128, 1);
  dim3 g1k(8, 128, 1);
  mma_gemm_qkv<<<dim3(4,128,1), blk, MMA_SMEM>>>(xsel, 0, layer, 0, 0, 0);   // Q only
  mma_gemm_qkv<<<dim3(8,128,1), blk, MMA_SMEM>>>(ssel, 0, layer, 0, 0, 512); // K,V
  kv_partial<<<dim3(SPLIT, NB*HH, 1), blk>>>(0, 0);
  kv_reduce<<<dim3(512, 1, 1), blk>>>(0, 0);
  msg_kernel<<<dim3(LSEQ/64, NB*HH, 1), blk>>>(0, 0);
  mma_gemm<0><<<gq,  blk, MMA_SMEM>>>(2, 0, 3, layer, 3, 0, CC, CC);       // msg@Wm -> m[0]
  ln_to_cat<<<dim3(ROWS,1,1), 128>>>(xsel, 0, 0, 0, gg1, bb1);
  mma_gemm<3><<<g1k, blk, MMA_SMEM>>>(4+xsel, 0, 4, layer, 0, 0, C2, C2);  // -> t[0]
  mma_gemm<0><<<gq,  blk, MMA_SMEM>>>(6, 0, 5, layer, 1, 0, CC, C2);       // -> k[0]
  ln_res<<<dim3(ROWS,1,1), 128>>>(xsel, 0, 0, 0, gg2, bb2);
}

extern "C" void kernel_launch(void* const* d_in, const int* in_sizes, int n_in,
                              void* d_out, int out_size)
{
  (void)in_sizes; (void)n_in; (void)out_size;
  const float* feat0 = (const float*)d_in[0];
  const float* feat1 = (const float*)d_in[1];
  const float* Wq = (const float*)d_in[2];
  const float* Wk = (const float*)d_in[3];
  const float* Wv = (const float*)d_in[4];
  const float* Wm = (const float*)d_in[5];
  const float* W1 = (const float*)d_in[6];
  const float* W2 = (const float*)d_in[7];
  const float* g1 = (const float*)d_in[8];
  const float* b1 = (const float*)d_in[9];
  const float* g2 = (const float*)d_in[10];
  const float* b2 = (const float*)d_in[11];

  cudaFuncSetAttribute(mma_gemm<0>, cudaFuncAttributeMaxDynamicSharedMemorySize, MMA_SMEM);
  cudaFuncSetAttribute(mma_gemm<3>, cudaFuncAttributeMaxDynamicSharedMemorySize, MMA_SMEM);
  cudaFuncSetAttribute(mma_gemm_qkv, cudaFuncAttributeMaxDynamicSharedMemorySize, MMA_SMEM);

  wprep_all<<<30720, 256>>>(Wq, Wk, Wv, Wm, W1, W2);
  copy_in<<<ELEMS4/256, 256>>>(feat0, feat1);

  for (int i = 0; i < NLAYERS; i++){
    const float* gg1 = g1 + (size_t)i*CC;
    const float* bb1 = b1 + (size_t)i*CC;
    const float* gg2 = g2 + (size_t)i*CC;
    const float* bb2 = b2 + (size_t)i*CC;
    if ((i & 1) == 0){
      enc_dual(i, gg1, bb1, gg2, bb2);
    } else {
      enc_single(0, 1, i, gg1, bb1, gg2, bb2);
      enc_single(1, 0, i, gg1, bb1, gg2, bb2);
    }
  }

  copy_out<<<ELEMS4/256, 256>>>((float*)d_out);
}

// round 16
// speedup vs baseline: 1.5455x; 1.3349x over previous
#include <cuda_runtime.h>
#include <cuda_fp16.h>
#include <math.h>
#include <stdint.h>

#define NB 4
#define LSEQ 4096
#define CC 512
#define C2 1024
#define HH 8
#define DD 64
#define ROWS (NB*LSEQ)          // 16384
#define SPLIT 32
#define SCHUNK (LSEQ/SPLIT)     // 128
#define NLAYERS 12
#define ELEMS (ROWS*CC)         // 8388608
#define ELEMS4 (ELEMS/4)
#define NQKV 1536

typedef __half h16;

// ---------------- device globals (no allocation) ----------------
__device__ float g_f0[ELEMS], g_f1[ELEMS];
__device__ float g_q[2][ELEMS], g_k[2][ELEMS], g_v[2][ELEMS], g_m[2][ELEMS];
__device__ float g_kvp[2][SPLIT*NB*HH*DD*DD];
__device__ float g_ksp[2][SPLIT*NB*HH*DD];
__device__ float g_kv[2][NB*HH*DD*DD];
__device__ float g_ksum[2][NB*HH*DD];

// fp16 activation shadows (x keeps hi/lo for QKV GEMM; others hi-only)
__device__ h16 s_xh0[ELEMS], s_xl0[ELEMS], s_xh1[ELEMS], s_xl1[ELEMS];
__device__ h16 s_mh[2][ELEMS], s_ml[2][ELEMS];
__device__ h16 s_ch0[ROWS*C2], s_cl0[ROWS*C2];
__device__ h16 s_ch1[ROWS*C2], s_cl1[ROWS*C2];
__device__ h16 s_th[2][ROWS*C2], s_tl[2][ROWS*C2];

// transposed fp16 weights: [N rows][K cols], per layer
__device__ h16 w_qkv[NLAYERS*NQKV*CC];   // rows 0-511 Wq, 512-1023 Wk, 1024-1535 Wv
__device__ h16 w_m[NLAYERS*CC*CC];
__device__ h16 w_1[NLAYERS*C2*C2];
__device__ h16 w_2[NLAYERS*CC*C2];

// ---------------- helpers ----------------
__device__ __forceinline__ uint32_t s2u(const void* p){
  uint32_t a;
  asm("{ .reg .u64 t; cvta.to.shared.u64 t, %1; cvt.u32.u64 %0, t; }" : "=r"(a) : "l"(p));
  return a;
}

__device__ __forceinline__ void hsplit_store4(h16* H, h16* L, size_t idx,
                                              float a, float b, float c, float d){
  h16 h0=__float2half(a), h1=__float2half(b), h2=__float2half(c), h3=__float2half(d);
  h16 l0=__float2half(a-__half2float(h0));
  h16 l1=__float2half(b-__half2float(h1));
  h16 l2=__float2half(c-__half2float(h2));
  h16 l3=__float2half(d-__half2float(h3));
  *(ushort4*)(H+idx) = make_ushort4(__half_as_ushort(h0), __half_as_ushort(h1),
                                    __half_as_ushort(h2), __half_as_ushort(h3));
  *(ushort4*)(L+idx) = make_ushort4(__half_as_ushort(l0), __half_as_ushort(l1),
                                    __half_as_ushort(l2), __half_as_ushort(l3));
}

__device__ __forceinline__ void hstore4(h16* H, size_t idx,
                                        float a, float b, float c, float d){
  *(ushort4*)(H+idx) = make_ushort4(
      __half_as_ushort(__float2half(a)), __half_as_ushort(__float2half(b)),
      __half_as_ushort(__float2half(c)), __half_as_ushort(__float2half(d)));
}

__device__ __forceinline__ void hstore2(h16* H, size_t idx, float a, float b){
  *(ushort2*)(H+idx) = make_ushort2(
      __half_as_ushort(__float2half(a)), __half_as_ushort(__float2half(b)));
}

__device__ __forceinline__ void cpasync16(uint32_t dst, const void* src){
  asm volatile("cp.async.cg.shared.global [%0], [%1], 16;" :: "r"(dst), "l"(src));
}

__device__ __forceinline__ void ldsm4(uint32_t* r, uint32_t addr){
  asm volatile("ldmatrix.sync.aligned.m8n8.x4.shared.b16 {%0,%1,%2,%3}, [%4];"
    : "=r"(r[0]),"=r"(r[1]),"=r"(r[2]),"=r"(r[3]) : "r"(addr));
}

__device__ __forceinline__ void mma16816(float* d, const uint32_t* a, const uint32_t* b){
  asm volatile("mma.sync.aligned.m16n8k16.row.col.f32.f16.f16.f32 "
    "{%0,%1,%2,%3},{%4,%5,%6,%7},{%8,%9},{%0,%1,%2,%3};"
    : "+f"(d[0]),"+f"(d[1]),"+f"(d[2]),"+f"(d[3])
    : "r"(a[0]),"r"(a[1]),"r"(a[2]),"r"(a[3]), "r"(b[0]),"r"(b[1]));
}

// swizzled byte offset within a tile (rows x 32 halves; 2 rows per 128B physrow)
__device__ __forceinline__ uint32_t swoff(int row, int c){
  int pr = row >> 1;
  int ch = ((row & 1)*4 + c) ^ (pr & 7);
  return (uint32_t)(pr*128 + ch*16);
}

// ---------------- operand selectors ----------------
// A: 0=x0, 1=x1, 2=msg[0], 3=msg[1], 4=cat0, 5=cat1, 6=t[0], 7=t[1]
__device__ __forceinline__ void apair(int s, const h16*& h, const h16*& l){
  switch(s){
    case 0: h=s_xh0;    l=s_xl0;    break;
    case 1: h=s_xh1;    l=s_xl1;    break;
    case 2: h=s_mh[0];  l=s_ml[0];  break;
    case 3: h=s_mh[1];  l=s_ml[1];  break;
    case 4: h=s_ch0;    l=s_cl0;    break;
    case 5: h=s_ch1;    l=s_cl1;    break;
    case 6: h=s_th[0];  l=s_tl[0];  break;
    default:h=s_th[1];  l=s_tl[1];  break;
  }
}
// B: 0 = Q rows of w_qkv, 3 = w_m, 4 = w_1, 5 = w_2
__device__ __forceinline__ const h16* bsel(int s, int layer){
  switch(s){
    case 0: return w_qkv + (size_t)layer*NQKV*CC;
    case 3: return w_m + (size_t)layer*CC*CC;
    case 4: return w_1 + (size_t)layer*C2*C2;
    default:return w_2 + (size_t)layer*CC*C2;
  }
}
// C: slot = s>>2, kind = s&3: 0=q,1=k,2=v,3=m
__device__ __forceinline__ float* cbuf(int s){
  int slot = s >> 2;
  switch(s & 3){
    case 0: return g_q[slot]; case 1: return g_k[slot];
    case 2: return g_v[slot]; default: return g_m[slot];
  }
}

// ---------------- split-fp16 GEMM via mma.sync ----------------
// CTA 128x128x32, warp 64x32, 4-stage cp.async pipeline.
// LO (compile-time in enclosing scope): 1 = use A-lo product, 0 = hi only.
#define NSTG 4
#define STG_BYTES 24576
#define MMA_SMEM (NSTG*STG_BYTES)

#define GEMM_CORE(gsrcAh, gsrcAl, gsrcB, Kc)                                         \
  const int lr0 = t >> 2, lc0 = t & 3;                                               \
  const int lm = lane >> 3, lrr = lane & 7;                                          \
  const h16* gsrc[3] = { gsrcAh, gsrcAl, gsrcB };                                    \
  float acc[4][4][4];                                                                \
  _Pragma("unroll") for (int i=0;i<4;i++)                                            \
  _Pragma("unroll") for (int j=0;j<4;j++)                                            \
  _Pragma("unroll") for (int q=0;q<4;q++) acc[i][j][q] = 0.f;                        \
  const int nc = (Kc) >> 5;                                                          \
  LOAD_STAGE(0, 0); LOAD_STAGE(1, 1); LOAD_STAGE(2, 2);                              \
  for (int c = 0; c < nc; c++){                                                      \
    if (c + 3 < nc) LOAD_STAGE((c+3)%NSTG, c+3);                                     \
    int rem = nc - 1 - c;                                                            \
    if (rem >= 3)      asm volatile("cp.async.wait_group 3;" ::: "memory");          \
    else if (rem == 2) asm volatile("cp.async.wait_group 2;" ::: "memory");          \
    else if (rem == 1) asm volatile("cp.async.wait_group 1;" ::: "memory");          \
    else               asm volatile("cp.async.wait_group 0;" ::: "memory");          \
    __syncthreads();                                                                 \
    const uint32_t base = sb + (c%NSTG)*STG_BYTES;                                   \
    _Pragma("unroll")                                                                \
    for (int k16 = 0; k16 < 2; k16++){                                               \
      uint32_t ah[4][4], al[4][4], bh[4][2];                                         \
      _Pragma("unroll")                                                              \
      for (int mt = 0; mt < 4; mt++){                                                \
        int row = wm*64 + mt*16 + (lm&1)*8 + lrr;                                    \
        int ch  = k16*2 + (lm>>1);                                                   \
        uint32_t o = swoff(row, ch);                                                 \
        ldsm4(ah[mt], base + o);                                                     \
        if (LO) ldsm4(al[mt], base + 8192 + o);                                      \
      }                                                                              \
      _Pragma("unroll")                                                              \
      for (int g = 0; g < 2; g++){                                                   \
        int row = wn*32 + g*16 + (lm>>1)*8 + lrr;                                    \
        int ch  = k16*2 + (lm&1);                                                    \
        uint32_t o = swoff(row, ch);                                                 \
        uint32_t r4[4];                                                              \
        ldsm4(r4, base + 16384 + o);                                                 \
        bh[g*2][0]=r4[0]; bh[g*2][1]=r4[1]; bh[g*2+1][0]=r4[2]; bh[g*2+1][1]=r4[3];  \
      }                                                                              \
      _Pragma("unroll")                                                              \
      for (int mt = 0; mt < 4; mt++)                                                 \
      _Pragma("unroll")                                                              \
        for (int nt = 0; nt < 4; nt++){                                              \
          mma16816(acc[mt][nt], ah[mt], bh[nt]);                                     \
          if (LO) mma16816(acc[mt][nt], al[mt], bh[nt]);                             \
        }                                                                            \
    }                                                                                \
    __syncthreads();                                                                 \
  }

#define LOAD_STAGE(stg, ck) do {                                              \
    uint32_t base_ = sb + (stg)*STG_BYTES;                                    \
    int k0_ = (ck)*32;                                                        \
    _Pragma("unroll")                                                         \
    for (int tl_=0; tl_<3; tl_++){                                            \
      if (!LO && tl_ == 1) continue;                                          \
      uint32_t tb_ = base_ + tl_*8192;                                        \
      const char* g_ = (const char*)(gsrc[tl_] + k0_);                        \
      cpasync16(tb_ + swoff(lr0,    lc0), g_ + ((size_t)lr0   *K + lc0*8)*2); \
      cpasync16(tb_ + swoff(lr0+64, lc0), g_ + ((size_t)(lr0+64)*K + lc0*8)*2);\
    }                                                                         \
    asm volatile("cp.async.commit_group;");                                   \
  } while(0)

// Generic GEMM: C[M,Nw] = epi( A @ B^T ). grid (Nw/128, M/128, nz).
// EPI: 0 none->fp32, 3 relu->fp16 hi-only into t[Csel]
template<int EPI, int LO>
__global__ __launch_bounds__(256)
void mma_gemm(int a0, int a1, int Bsel, int layer, int c0, int c1, int Nw, int K)
{
  extern __shared__ char smc[];
  const uint32_t sb = s2u(smc);
  const int z = blockIdx.z;
  const int Asel = z ? a1 : a0;
  const int Csel = z ? c1 : c0;

  const h16 *Ah,*Al;
  apair(Asel, Ah, Al);
  const h16* Bh = bsel(Bsel, layer);

  const int t = threadIdx.x, lane = t & 31, wid = t >> 5;
  const int wm = wid & 1, wn = wid >> 1;
  const int bm = blockIdx.y*128, bn = blockIdx.x*128;

  GEMM_CORE(Ah + (size_t)bm*K, Al + (size_t)bm*K, Bh + (size_t)bn*K, K)

  const int er = bm + wm*64 + (lane>>2);
  const int ec = bn + wn*32 + 2*(lane&3);
#pragma unroll
  for (int mt = 0; mt < 4; mt++){
#pragma unroll
    for (int nt = 0; nt < 4; nt++){
      int row = er + mt*16;
      int col = ec + nt*8;
      float v0 = acc[mt][nt][0], v1 = acc[mt][nt][1];
      float v2 = acc[mt][nt][2], v3 = acc[mt][nt][3];
      if (EPI == 3){
        v0 = v0 > 0.f ? v0 : 0.f; v1 = v1 > 0.f ? v1 : 0.f;
        v2 = v2 > 0.f ? v2 : 0.f; v3 = v3 > 0.f ? v3 : 0.f;
        h16* TH = s_th[Csel];
        hstore2(TH, (size_t)row*Nw + col, v0, v1);
        hstore2(TH, (size_t)(row+8)*Nw + col, v2, v3);
      } else {
        float* C = cbuf(Csel);
        *(float2*)(C + (size_t)row*Nw + col)     = make_float2(v0, v1);
        *(float2*)(C + (size_t)(row+8)*Nw + col) = make_float2(v2, v3);
      }
    }
  }
}

// Fused QKV/KV GEMM (full hi/lo): column segment selects epilogue and output.
// grid (nseg, 128, nz); z selects (a0,slot0)/(a1,slot1).
__global__ __launch_bounds__(256)
void mma_gemm_qkv(int a0, int a1, int layer, int slot0, int slot1, int rowoff)
{
  extern __shared__ char smc[];
  const uint32_t sb = s2u(smc);
  const int z = blockIdx.z;
  const int Asel = z ? a1 : a0;
  const int slot = z ? slot1 : slot0;
  const int K = CC;
  enum { LO = 1 };

  const h16 *Ah,*Al;
  apair(Asel, Ah, Al);
  const int grow = rowoff + blockIdx.x*128;       // global N row in w_qkv
  const int kind = grow >> 9;                     // 0=q,1=k,2=v
  const int cbase = grow & 511;
  const h16* Bh = w_qkv + (size_t)layer*NQKV*CC + (size_t)grow*CC;

  const int t = threadIdx.x, lane = t & 31, wid = t >> 5;
  const int wm = wid & 1, wn = wid >> 1;
  const int bm = blockIdx.y*128;

  GEMM_CORE(Ah + (size_t)bm*K, Al + (size_t)bm*K, Bh, K)

  float* C = cbuf(slot*4 + kind);
  const bool do_elu = (kind < 2);
  const int er = bm + wm*64 + (lane>>2);
  const int ec = cbase + wn*32 + 2*(lane&3);
#pragma unroll
  for (int mt = 0; mt < 4; mt++){
#pragma unroll
    for (int nt = 0; nt < 4; nt++){
      int row = er + mt*16;
      int col = ec + nt*8;
      float v0 = acc[mt][nt][0], v1 = acc[mt][nt][1];
      float v2 = acc[mt][nt][2], v3 = acc[mt][nt][3];
      if (do_elu){
        v0 = v0 > 0.f ? v0 + 1.f : expf(v0);
        v1 = v1 > 0.f ? v1 + 1.f : expf(v1);
        v2 = v2 > 0.f ? v2 + 1.f : expf(v2);
        v3 = v3 > 0.f ? v3 + 1.f : expf(v3);
      }
      *(float2*)(C + (size_t)row*CC + col)     = make_float2(v0, v1);
      *(float2*)(C + (size_t)(row+8)*CC + col) = make_float2(v2, v3);
    }
  }
}

// ---------------- weight prep: one launch, transpose + fp16 ----------------
__global__ __launch_bounds__(256)
void wprep_all(const float* __restrict__ Wq, const float* __restrict__ Wk,
               const float* __restrict__ Wv, const float* __restrict__ Wm,
               const float* __restrict__ W1, const float* __restrict__ W2)
{
  int id = blockIdx.x;
  int type, l, n0, k0, K, N;
  const float* src;
  h16* dst; size_t dstride;
  if (id < 12288){                 // q,k,v,m
    type = id / 3072; id %= 3072;
    l = id / 256; id %= 256;
    n0 = (id / 16) * 32; k0 = (id % 16) * 32;
    K = CC; N = CC;
    switch(type){
      case 0: src=Wq; dst=w_qkv + (size_t)l*NQKV*CC;                 break;
      case 1: src=Wk; dst=w_qkv + (size_t)l*NQKV*CC + (size_t)512*CC; break;
      case 2: src=Wv; dst=w_qkv + (size_t)l*NQKV*CC + (size_t)1024*CC;break;
      default:src=Wm; dst=w_m  + (size_t)l*CC*CC;                    break;
    }
    src += (size_t)l*CC*CC;
    dstride = CC;
  } else if (id < 24576){          // w1
    id -= 12288;
    l = id / 1024; id %= 1024;
    n0 = (id / 32) * 32; k0 = (id % 32) * 32;
    K = C2; N = C2;
    src = W1 + (size_t)l*C2*C2;
    dst = w_1 + (size_t)l*C2*C2;
    dstride = C2;
  } else {                         // w2
    id -= 24576;
    l = id / 512; id %= 512;
    n0 = (id / 32) * 32; k0 = (id % 32) * 32;
    K = C2; N = CC;
    src = W2 + (size_t)l*C2*CC;
    dst = w_2 + (size_t)l*CC*C2;
    dstride = C2;
  }
  __shared__ float tile[32][33];
  const int tx = threadIdx.x & 31, ty = threadIdx.x >> 5;
#pragma unroll
  for (int i = 0; i < 4; i++){
    int r = ty + i*8;
    tile[r][tx] = src[(size_t)(k0+r)*N + n0 + tx];
  }
  __syncthreads();
#pragma unroll
  for (int i = 0; i < 4; i++){
    int r = ty + i*8;
    dst[(size_t)(n0+r)*dstride + k0 + tx] = __float2half(tile[tx][r]);
  }
}

// ---------------- attention: KV split-K (deterministic) ----------------
__global__ __launch_bounds__(256)
void kv_partial(int s0, int s1)
{
  const int slot = blockIdx.z ? s1 : s0;
  const int nh = blockIdx.y, part = blockIdx.x;
  const int n = nh >> 3, h = nh & 7;
  __shared__ float Ks[32][68];
  __shared__ float Vs[32][68];
  const int t = threadIdx.x;
  const int tx = t & 15, ty = t >> 4;
  const float* Kb = g_k[slot] + (size_t)n*LSEQ*CC + h*DD;
  const float* Vb = g_v[slot] + (size_t)n*LSEQ*CC + h*DD;
  float acc[4][4] = {};
  float ksum = 0.f;
  const int send = part*SCHUNK + SCHUNK;
  for (int s0i = part*SCHUNK; s0i < send; s0i += 32){
#pragma unroll
    for (int p = 0; p < 2; p++){
      int idx = t + p*256;
      int r = idx >> 4, c4 = (idx & 15) << 2;
      *(float4*)&Ks[r][c4] = *(const float4*)(Kb + (size_t)(s0i+r)*CC + c4);
      *(float4*)&Vs[r][c4] = *(const float4*)(Vb + (size_t)(s0i+r)*CC + c4);
    }
    __syncthreads();
    if (t < DD){
#pragma unroll
      for (int kk = 0; kk < 32; kk++) ksum += Ks[kk][t];
    }
#pragma unroll
    for (int kk = 0; kk < 32; kk++){
      float4 a = *(const float4*)&Ks[kk][ty*4];
      float4 b = *(const float4*)&Vs[kk][tx*4];
      float ar[4]={a.x,a.y,a.z,a.w}, br[4]={b.x,b.y,b.z,b.w};
#pragma unroll
      for (int i=0;i<4;i++)
#pragma unroll
        for (int j=0;j<4;j++) acc[i][j] = fmaf(ar[i],br[j],acc[i][j]);
    }
    __syncthreads();
  }
  float* dst = g_kvp[slot] + ((size_t)part*NB*HH + nh)*DD*DD;
#pragma unroll
  for (int i=0;i<4;i++)
    *(float4*)&dst[(ty*4+i)*DD + tx*4] =
        make_float4(acc[i][0],acc[i][1],acc[i][2],acc[i][3]);
  if (t < DD) g_ksp[slot][(size_t)part*NB*HH*DD + nh*DD + t] = ksum;
}

__global__ __launch_bounds__(256)
void kv_reduce(int s0, int s1)
{
  const int slot = blockIdx.z ? s1 : s0;
  int i = blockIdx.x*256 + threadIdx.x;
  if (i < NB*HH*DD*DD){
    float s = 0.f;
#pragma unroll
    for (int p=0;p<SPLIT;p++) s += g_kvp[slot][(size_t)p*NB*HH*DD*DD + i];
    g_kv[slot][i] = s;
  }
  if (i < NB*HH*DD){
    float s=0.f;
#pragma unroll
    for (int p=0;p<SPLIT;p++) s += g_ksp[slot][p*NB*HH*DD + i];
    g_ksum[slot][i] = s;
  }
}

// msg = (Q @ KVu) / (Q.Ksum+eps)  -> fp16 hi only
__global__ __launch_bounds__(256)
void msg_kernel(int s0, int s1)
{
  const int slot = blockIdx.z ? s1 : s0;
  const int nh = blockIdx.y;
  const int n = nh >> 3, h = nh & 7;
  const int l0 = blockIdx.x * 64;
  __shared__ float Qs[64][68];
  __shared__ float KVs[64][68];
  __shared__ float ksm[64];
  __shared__ float zrow[64];
  const int t = threadIdx.x;
  const int tx = t & 15, ty = t >> 4;
  const float* Qb  = g_q[slot]  + (size_t)n*LSEQ*CC + h*DD;
  const float* KVb = g_kv[slot] + (size_t)nh*DD*DD;
#pragma unroll
  for (int p=0;p<4;p++){
    int idx = t + p*256;
    int r = idx >> 4, c4 = (idx & 15) << 2;
    float4 q = *(const float4*)(Qb + (size_t)(l0+r)*CC + c4);
    Qs[c4+0][r]=q.x; Qs[c4+1][r]=q.y; Qs[c4+2][r]=q.z; Qs[c4+3][r]=q.w;
    *(float4*)&KVs[r][c4] = *(const float4*)(KVb + r*DD + c4);
  }
  if (t < DD) ksm[t] = g_ksum[slot][nh*DD + t];
  __syncthreads();
  if (t < DD){
    float dn = 0.f;
#pragma unroll
    for (int d=0; d<DD; d++) dn = fmaf(Qs[d][t], ksm[d], dn);
    zrow[t] = 1.0f / (dn + 1e-6f);
  }
  __syncthreads();
  float acc[4][4] = {};
#pragma unroll
  for (int kk=0; kk<DD; kk++){
    float4 a = *(const float4*)&Qs[kk][ty*4];
    float4 b = *(const float4*)&KVs[kk][tx*4];
    float ar[4]={a.x,a.y,a.z,a.w}, br[4]={b.x,b.y,b.z,b.w};
#pragma unroll
    for (int i=0;i<4;i++)
#pragma unroll
      for (int j=0;j<4;j++) acc[i][j] = fmaf(ar[i],br[j],acc[i][j]);
  }
#pragma unroll
  for (int i=0;i<4;i++){
    int m = ty*4+i;
    float zz = zrow[m];
    size_t base = ((size_t)(n*LSEQ + l0 + m))*CC + h*DD + tx*4;
    hstore4(s_mh[slot], base, acc[i][0]*zz, acc[i][1]*zz, acc[i][2]*zz, acc[i][3]*zz);
  }
}

// ---------------- LN kernels ----------------
__device__ __forceinline__ void ln_core(const float4& v, int t, float& mu, float& rs)
{
  float s  = v.x+v.y+v.z+v.w;
  float s2 = v.x*v.x + v.y*v.y + v.z*v.z + v.w*v.w;
  __shared__ float sh[8];
#pragma unroll
  for (int o=16;o>0;o>>=1){
    s  += __shfl_xor_sync(0xffffffffu, s, o);
    s2 += __shfl_xor_sync(0xffffffffu, s2, o);
  }
  if ((t & 31) == 0){ sh[t>>5] = s; sh[4 + (t>>5)] = s2; }
  __syncthreads();
  s  = sh[0]+sh[1]+sh[2]+sh[3];
  s2 = sh[4]+sh[5]+sh[6]+sh[7];
  mu = s * (1.0f/CC);
  float var = s2 * (1.0f/CC) - mu*mu;
  rs = rsqrtf(var + 1e-5f);
}

// LN(g_m[slot]) -> cat{xsel}[:, 512:1024] fp16 hi only
__global__ __launch_bounds__(128)
void ln_to_cat(int x0, int x1, int s0, int s1,
               const float* __restrict__ gamma, const float* __restrict__ beta)
{
  const int xsel = blockIdx.z ? x1 : x0;
  const int slot = blockIdx.z ? s1 : s0;
  const int row = blockIdx.x;
  const int t = threadIdx.x;
  float4 v = *(const float4*)(g_m[slot] + (size_t)row*CC + t*4);
  float mu, rs;
  ln_core(v, t, mu, rs);
  float4 g = *(const float4*)(gamma + t*4);
  float4 b = *(const float4*)(beta + t*4);
  float o0 = (v.x-mu)*rs*g.x + b.x;
  float o1 = (v.y-mu)*rs*g.y + b.y;
  float o2 = (v.z-mu)*rs*g.z + b.z;
  float o3 = (v.w-mu)*rs*g.w + b.w;
  h16* ch = xsel ? s_ch1 : s_ch0;
  hstore4(ch, (size_t)row*C2 + CC + t*4, o0, o1, o2, o3);
}

// x = x + LN(g_k[slot]); writes fp32 x, fp16 hi/lo x-shadow, cat x-half hi only
__global__ __launch_bounds__(128)
void ln_res(int x0, int x1, int s0, int s1,
            const float* __restrict__ gamma, const float* __restrict__ beta)
{
  const int xsel = blockIdx.z ? x1 : x0;
  const int slot = blockIdx.z ? s1 : s0;
  const int row = blockIdx.x;
  const int t = threadIdx.x;
  float4 v = *(const float4*)(g_k[slot] + (size_t)row*CC + t*4);
  float mu, rs;
  ln_core(v, t, mu, rs);
  float4 g = *(const float4*)(gamma + t*4);
  float4 b = *(const float4*)(beta + t*4);
  float* x = xsel ? g_f1 : g_f0;
  h16* xh = xsel ? s_xh1 : s_xh0;
  h16* xl = xsel ? s_xl1 : s_xl0;
  h16* ch = xsel ? s_ch1 : s_ch0;
  float4 r = *(const float4*)(x + (size_t)row*CC + t*4);
  float o0 = (v.x-mu)*rs*g.x + b.x + r.x;
  float o1 = (v.y-mu)*rs*g.y + b.y + r.y;
  float o2 = (v.z-mu)*rs*g.z + b.z + r.z;
  float o3 = (v.w-mu)*rs*g.w + b.w + r.w;
  *(float4*)(x + (size_t)row*CC + t*4) = make_float4(o0,o1,o2,o3);
  hsplit_store4(xh, xl, (size_t)row*CC + t*4, o0, o1, o2, o3);
  hstore4(ch, (size_t)row*C2 + t*4, o0, o1, o2, o3);
}

__global__ __launch_bounds__(256)
void copy_in(const float* __restrict__ f0, const float* __restrict__ f1)
{
  size_t i = (size_t)blockIdx.x*256 + threadIdx.x;
  float4 a = ((const float4*)f0)[i];
  float4 b = ((const float4*)f1)[i];
  ((float4*)g_f0)[i] = a;
  ((float4*)g_f1)[i] = b;
  size_t row = i >> 7, c4 = i & 127;
  hsplit_store4(s_xh0, s_xl0, i*4, a.x, a.y, a.z, a.w);
  hsplit_store4(s_xh1, s_xl1, i*4, b.x, b.y, b.z, b.w);
  hstore4(s_ch0, row*C2 + c4*4, a.x, a.y, a.z, a.w);
  hstore4(s_ch1, row*C2 + c4*4, b.x, b.y, b.z, b.w);
}

__global__ __launch_bounds__(256)
void copy_out(float* __restrict__ out)
{
  size_t i = (size_t)blockIdx.x*256 + threadIdx.x;
  ((float4*)out)[i]          = ((const float4*)g_f0)[i];
  ((float4*)out)[i + ELEMS4] = ((const float4*)g_f1)[i];
}

// ---------------- host-side layer drivers ----------------
static void enc_dual(int layer,
                     const float* gg1, const float* bb1,
                     const float* gg2, const float* bb2)
{
  dim3 blk(256);
  dim3 gq(4, 128, 2);
  dim3 g1k(8, 128, 2);
  mma_gemm_qkv<<<dim3(12,128,2), blk, MMA_SMEM>>>(0, 1, layer, 0, 1, 0);     // QKV fused
  kv_partial<<<dim3(SPLIT, NB*HH, 2), blk>>>(0, 1);
  kv_reduce<<<dim3(512, 1, 2), blk>>>(0, 1);
  msg_kernel<<<dim3(LSEQ/64, NB*HH, 2), blk>>>(0, 1);
  mma_gemm<0,0><<<gq,  blk, MMA_SMEM>>>(2, 3, 3, layer, 3, 7, CC, CC);       // msg@Wm -> m
  ln_to_cat<<<dim3(ROWS,1,2), 128>>>(0, 1, 0, 1, gg1, bb1);
  mma_gemm<3,0><<<g1k, blk, MMA_SMEM>>>(4, 5, 4, layer, 0, 1, C2, C2);       // relu(cat@W1) -> t
  mma_gemm<0,0><<<gq,  blk, MMA_SMEM>>>(6, 7, 5, layer, 1, 5, CC, C2);       // t@W2 -> k
  ln_res<<<dim3(ROWS,1,2), 128>>>(0, 1, 0, 1, gg2, bb2);
}

static void enc_single(int xsel, int ssel, int layer,
                       const float* gg1, const float* bb1,
                       const float* gg2, const float* bb2)
{
  dim3 blk(256);
  dim3 gq(4, 128, 1);
  dim3 g1k(8, 128, 1);
  mma_gemm_qkv<<<dim3(4,128,1), blk, MMA_SMEM>>>(xsel, 0, layer, 0, 0, 0);   // Q only
  mma_gemm_qkv<<<dim3(8,128,1), blk, MMA_SMEM>>>(ssel, 0, layer, 0, 0, 512); // K,V
  kv_partial<<<dim3(SPLIT, NB*HH, 1), blk>>>(0, 0);
  kv_reduce<<<dim3(512, 1, 1), blk>>>(0, 0);
  msg_kernel<<<dim3(LSEQ/64, NB*HH, 1), blk>>>(0, 0);
  mma_gemm<0,0><<<gq,  blk, MMA_SMEM>>>(2, 0, 3, layer, 3, 0, CC, CC);       // msg@Wm -> m[0]
  ln_to_cat<<<dim3(ROWS,1,1), 128>>>(xsel, 0, 0, 0, gg1, bb1);
  mma_gemm<3,0><<<g1k, blk, MMA_SMEM>>>(4+xsel, 0, 4, layer, 0, 0, C2, C2);  // -> t[0]
  mma_gemm<0,0><<<gq,  blk, MMA_SMEM>>>(6, 0, 5, layer, 1, 0, CC, C2);       // -> k[0]
  ln_res<<<dim3(ROWS,1,1), 128>>>(xsel, 0, 0, 0, gg2, bb2);
}

extern "C" void kernel_launch(void* const* d_in, const int* in_sizes, int n_in,
                              void* d_out, int out_size)
{
  (void)in_sizes; (void)n_in; (void)out_size;
  const float* feat0 = (const float*)d_in[0];
  const float* feat1 = (const float*)d_in[1];
  const float* Wq = (const float*)d_in[2];
  const float* Wk = (const float*)d_in[3];
  const float* Wv = (const float*)d_in[4];
  const float* Wm = (const float*)d_in[5];
  const float* W1 = (const float*)d_in[6];
  const float* W2 = (const float*)d_in[7];
  const float* g1 = (const float*)d_in[8];
  const float* b1 = (const float*)d_in[9];
  const float* g2 = (const float*)d_in[10];
  const float* b2 = (const float*)d_in[11];

  cudaFuncSetAttribute((const void*)mma_gemm<0,0>, cudaFuncAttributeMaxDynamicSharedMemorySize, MMA_SMEM);
  cudaFuncSetAttribute((const void*)mma_gemm<3,0>, cudaFuncAttributeMaxDynamicSharedMemorySize, MMA_SMEM);
  cudaFuncSetAttribute((const void*)mma_gemm_qkv, cudaFuncAttributeMaxDynamicSharedMemorySize, MMA_SMEM);

  wprep_all<<<30720, 256>>>(Wq, Wk, Wv, Wm, W1, W2);
  copy_in<<<ELEMS4/256, 256>>>(feat0, feat1);

  for (int i = 0; i < NLAYERS; i++){
    const float* gg1 = g1 + (size_t)i*CC;
    const float* bb1 = b1 + (size_t)i*CC;
    const float* gg2 = g2 + (size_t)i*CC;
    const float* bb2 = b2 + (size_t)i*CC;
    if ((i & 1) == 0){
      enc_dual(i, gg1, bb1, gg2, bb2);
    } else {
      enc_single(0, 1, i, gg1, bb1, gg2, bb2);
      enc_single(1, 0, i, gg1, bb1, gg2, bb2);
    }
  }

  copy_out<<<ELEMS4/256, 256>>>((float*)d_out);
}

// round 17
// speedup vs baseline: 1.7789x; 1.1510x over previous
#include <cuda_runtime.h>
#include <cuda_fp16.h>
#include <math.h>
#include <stdint.h>

#define NB 4
#define LSEQ 4096
#define CC 512
#define C2 1024
#define HH 8
#define DD 64
#define ROWS (NB*LSEQ)          // 16384
#define SPLIT 32
#define SCHUNK (LSEQ/SPLIT)     // 128
#define NLAYERS 12
#define ELEMS (ROWS*CC)         // 8388608
#define ELEMS4 (ELEMS/4)
#define NQKV 1536

typedef __half h16;

// ---------------- device globals (no allocation) ----------------
__device__ float g_f0[ELEMS], g_f1[ELEMS];
__device__ float g_q[2][ELEMS], g_k[2][ELEMS], g_v[2][ELEMS], g_m[2][ELEMS];
__device__ float g_kvp[2][SPLIT*NB*HH*DD*DD];
__device__ float g_ksp[2][SPLIT*NB*HH*DD];
__device__ float g_kv[2][NB*HH*DD*DD];
__device__ float g_ksum[2][NB*HH*DD];

// fp16 activation shadows (hi-only everywhere now)
__device__ h16 s_xh0[ELEMS], s_xh1[ELEMS];
__device__ h16 s_mh[2][ELEMS];
__device__ h16 s_ch0[ROWS*C2];
__device__ h16 s_ch1[ROWS*C2];
__device__ h16 s_th[2][ROWS*C2];

// transposed fp16 weights: [N rows][K cols], per layer
__device__ h16 w_qkv[NLAYERS*NQKV*CC];   // rows 0-511 Wq, 512-1023 Wk, 1024-1535 Wv
__device__ h16 w_m[NLAYERS*CC*CC];
__device__ h16 w_1[NLAYERS*C2*C2];
__device__ h16 w_2[NLAYERS*CC*C2];

// ---------------- helpers ----------------
__device__ __forceinline__ uint32_t s2u(const void* p){
  uint32_t a;
  asm("{ .reg .u64 t; cvta.to.shared.u64 t, %1; cvt.u32.u64 %0, t; }" : "=r"(a) : "l"(p));
  return a;
}

__device__ __forceinline__ void hstore4(h16* H, size_t idx,
                                        float a, float b, float c, float d){
  *(ushort4*)(H+idx) = make_ushort4(
      __half_as_ushort(__float2half(a)), __half_as_ushort(__float2half(b)),
      __half_as_ushort(__float2half(c)), __half_as_ushort(__float2half(d)));
}

__device__ __forceinline__ void hstore2(h16* H, size_t idx, float a, float b){
  *(ushort2*)(H+idx) = make_ushort2(
      __half_as_ushort(__float2half(a)), __half_as_ushort(__float2half(b)));
}

__device__ __forceinline__ void cpasync16(uint32_t dst, const void* src){
  asm volatile("cp.async.cg.shared.global [%0], [%1], 16;" :: "r"(dst), "l"(src));
}

__device__ __forceinline__ void ldsm4(uint32_t* r, uint32_t addr){
  asm volatile("ldmatrix.sync.aligned.m8n8.x4.shared.b16 {%0,%1,%2,%3}, [%4];"
    : "=r"(r[0]),"=r"(r[1]),"=r"(r[2]),"=r"(r[3]) : "r"(addr));
}

__device__ __forceinline__ void mma16816(float* d, const uint32_t* a, const uint32_t* b){
  asm volatile("mma.sync.aligned.m16n8k16.row.col.f32.f16.f16.f32 "
    "{%0,%1,%2,%3},{%4,%5,%6,%7},{%8,%9},{%0,%1,%2,%3};"
    : "+f"(d[0]),"+f"(d[1]),"+f"(d[2]),"+f"(d[3])
    : "r"(a[0]),"r"(a[1]),"r"(a[2]),"r"(a[3]), "r"(b[0]),"r"(b[1]));
}

// swizzled byte offset within a tile (rows x 32 halves; 2 rows per 128B physrow)
__device__ __forceinline__ uint32_t swoff(int row, int c){
  int pr = row >> 1;
  int ch = ((row & 1)*4 + c) ^ (pr & 7);
  return (uint32_t)(pr*128 + ch*16);
}

// ---------------- operand selectors ----------------
// A (hi-only): 0=x0, 1=x1, 2=msg[0], 3=msg[1], 4=cat0, 5=cat1, 6=t[0], 7=t[1]
__device__ __forceinline__ const h16* asel(int s){
  switch(s){
    case 0: return s_xh0;
    case 1: return s_xh1;
    case 2: return s_mh[0];
    case 3: return s_mh[1];
    case 4: return s_ch0;
    case 5: return s_ch1;
    case 6: return s_th[0];
    default:return s_th[1];
  }
}
// B: 3 = w_m, 4 = w_1, 5 = w_2
__device__ __forceinline__ const h16* bsel(int s, int layer){
  switch(s){
    case 3: return w_m + (size_t)layer*CC*CC;
    case 4: return w_1 + (size_t)layer*C2*C2;
    default:return w_2 + (size_t)layer*CC*C2;
  }
}
// C: slot = s>>2, kind = s&3: 0=q,1=k,2=v,3=m
__device__ __forceinline__ float* cbuf(int s){
  int slot = s >> 2;
  switch(s & 3){
    case 0: return g_q[slot]; case 1: return g_k[slot];
    case 2: return g_v[slot]; default: return g_m[slot];
  }
}

// ---------------- fp16 GEMM via mma.sync (hi-only) ----------------
// CTA 128x128x32, warp 64x32, 4-stage cp.async pipeline.
#define NSTG 4
#define STG_BYTES 24576
#define MMA_SMEM (NSTG*STG_BYTES)

#define GEMM_CORE(gsrcA, gsrcB, Kc)                                                  \
  const int lr0 = t >> 2, lc0 = t & 3;                                               \
  const int lm = lane >> 3, lrr = lane & 7;                                          \
  const h16* gsrc[2] = { gsrcA, gsrcB };                                             \
  float acc[4][4][4];                                                                \
  _Pragma("unroll") for (int i=0;i<4;i++)                                            \
  _Pragma("unroll") for (int j=0;j<4;j++)                                            \
  _Pragma("unroll") for (int q=0;q<4;q++) acc[i][j][q] = 0.f;                        \
  const int nc = (Kc) >> 5;                                                          \
  LOAD_STAGE(0, 0); LOAD_STAGE(1, 1); LOAD_STAGE(2, 2);                              \
  for (int c = 0; c < nc; c++){                                                      \
    if (c + 3 < nc) LOAD_STAGE((c+3)%NSTG, c+3);                                     \
    int rem = nc - 1 - c;                                                            \
    if (rem >= 3)      asm volatile("cp.async.wait_group 3;" ::: "memory");          \
    else if (rem == 2) asm volatile("cp.async.wait_group 2;" ::: "memory");          \
    else if (rem == 1) asm volatile("cp.async.wait_group 1;" ::: "memory");          \
    else               asm volatile("cp.async.wait_group 0;" ::: "memory");          \
    __syncthreads();                                                                 \
    const uint32_t base = sb + (c%NSTG)*STG_BYTES;                                   \
    _Pragma("unroll")                                                                \
    for (int k16 = 0; k16 < 2; k16++){                                               \
      uint32_t ah[4][4], bh[4][2];                                                   \
      _Pragma("unroll")                                                              \
      for (int mt = 0; mt < 4; mt++){                                                \
        int row = wm*64 + mt*16 + (lm&1)*8 + lrr;                                    \
        int ch  = k16*2 + (lm>>1);                                                   \
        ldsm4(ah[mt], base + swoff(row, ch));                                        \
      }                                                                              \
      _Pragma("unroll")                                                              \
      for (int g = 0; g < 2; g++){                                                   \
        int row = wn*32 + g*16 + (lm>>1)*8 + lrr;                                    \
        int ch  = k16*2 + (lm&1);                                                    \
        uint32_t r4[4];                                                              \
        ldsm4(r4, base + 8192 + swoff(row, ch));                                     \
        bh[g*2][0]=r4[0]; bh[g*2][1]=r4[1]; bh[g*2+1][0]=r4[2]; bh[g*2+1][1]=r4[3];  \
      }                                                                              \
      _Pragma("unroll")                                                              \
      for (int mt = 0; mt < 4; mt++)                                                 \
      _Pragma("unroll")                                                              \
        for (int nt = 0; nt < 4; nt++)                                               \
          mma16816(acc[mt][nt], ah[mt], bh[nt]);                                     \
    }                                                                                \
    __syncthreads();                                                                 \
  }

#define LOAD_STAGE(stg, ck) do {                                              \
    uint32_t base_ = sb + (stg)*STG_BYTES;                                    \
    int k0_ = (ck)*32;                                                        \
    _Pragma("unroll")                                                         \
    for (int tl_=0; tl_<2; tl_++){                                            \
      uint32_t tb_ = base_ + tl_*8192;                                        \
      const char* g_ = (const char*)(gsrc[tl_] + k0_);                        \
      cpasync16(tb_ + swoff(lr0,    lc0), g_ + ((size_t)lr0   *K + lc0*8)*2); \
      cpasync16(tb_ + swoff(lr0+64, lc0), g_ + ((size_t)(lr0+64)*K + lc0*8)*2);\
    }                                                                         \
    asm volatile("cp.async.commit_group;");                                   \
  } while(0)

// Generic GEMM: C[M,Nw] = epi( A @ B^T ). grid (Nw/128, M/128, nz).
// EPI: 0 none->fp32, 3 relu->fp16 into t[Csel]
template<int EPI>
__global__ __launch_bounds__(256)
void mma_gemm(int a0, int a1, int Bsel, int layer, int c0, int c1, int Nw, int K)
{
  extern __shared__ char smc[];
  const uint32_t sb = s2u(smc);
  const int z = blockIdx.z;
  const int Asel = z ? a1 : a0;
  const int Csel = z ? c1 : c0;

  const h16* Ah = asel(Asel);
  const h16* Bh = bsel(Bsel, layer);

  const int t = threadIdx.x, lane = t & 31, wid = t >> 5;
  const int wm = wid & 1, wn = wid >> 1;
  const int bm = blockIdx.y*128, bn = blockIdx.x*128;

  GEMM_CORE(Ah + (size_t)bm*K, Bh + (size_t)bn*K, K)

  const int er = bm + wm*64 + (lane>>2);
  const int ec = bn + wn*32 + 2*(lane&3);
#pragma unroll
  for (int mt = 0; mt < 4; mt++){
#pragma unroll
    for (int nt = 0; nt < 4; nt++){
      int row = er + mt*16;
      int col = ec + nt*8;
      float v0 = acc[mt][nt][0], v1 = acc[mt][nt][1];
      float v2 = acc[mt][nt][2], v3 = acc[mt][nt][3];
      if (EPI == 3){
        v0 = v0 > 0.f ? v0 : 0.f; v1 = v1 > 0.f ? v1 : 0.f;
        v2 = v2 > 0.f ? v2 : 0.f; v3 = v3 > 0.f ? v3 : 0.f;
        h16* TH = s_th[Csel];
        hstore2(TH, (size_t)row*Nw + col, v0, v1);
        hstore2(TH, (size_t)(row+8)*Nw + col, v2, v3);
      } else {
        float* C = cbuf(Csel);
        *(float2*)(C + (size_t)row*Nw + col)     = make_float2(v0, v1);
        *(float2*)(C + (size_t)(row+8)*Nw + col) = make_float2(v2, v3);
      }
    }
  }
}

// Fused QKV/KV GEMM (hi-only A): column segment selects epilogue and output.
// grid (nseg, 128, nz); z selects (a0,slot0)/(a1,slot1).
__global__ __launch_bounds__(256)
void mma_gemm_qkv(int a0, int a1, int layer, int slot0, int slot1, int rowoff)
{
  extern __shared__ char smc[];
  const uint32_t sb = s2u(smc);
  const int z = blockIdx.z;
  const int Asel = z ? a1 : a0;
  const int slot = z ? slot1 : slot0;
  const int K = CC;

  const h16* Ah = asel(Asel);
  const int grow = rowoff + blockIdx.x*128;       // global N row in w_qkv
  const int kind = grow >> 9;                     // 0=q,1=k,2=v
  const int cbase = grow & 511;
  const h16* Bh = w_qkv + (size_t)layer*NQKV*CC + (size_t)grow*CC;

  const int t = threadIdx.x, lane = t & 31, wid = t >> 5;
  const int wm = wid & 1, wn = wid >> 1;
  const int bm = blockIdx.y*128;

  GEMM_CORE(Ah + (size_t)bm*K, Bh, K)

  float* C = cbuf(slot*4 + kind);
  const bool do_elu = (kind < 2);
  const int er = bm + wm*64 + (lane>>2);
  const int ec = cbase + wn*32 + 2*(lane&3);
#pragma unroll
  for (int mt = 0; mt < 4; mt++){
#pragma unroll
    for (int nt = 0; nt < 4; nt++){
      int row = er + mt*16;
      int col = ec + nt*8;
      float v0 = acc[mt][nt][0], v1 = acc[mt][nt][1];
      float v2 = acc[mt][nt][2], v3 = acc[mt][nt][3];
      if (do_elu){
        v0 = v0 > 0.f ? v0 + 1.f : expf(v0);
        v1 = v1 > 0.f ? v1 + 1.f : expf(v1);
        v2 = v2 > 0.f ? v2 + 1.f : expf(v2);
        v3 = v3 > 0.f ? v3 + 1.f : expf(v3);
      }
      *(float2*)(C + (size_t)row*CC + col)     = make_float2(v0, v1);
      *(float2*)(C + (size_t)(row+8)*CC + col) = make_float2(v2, v3);
    }
  }
}

// ---------------- weight prep: one launch, transpose + fp16 ----------------
__global__ __launch_bounds__(256)
void wprep_all(const float* __restrict__ Wq, const float* __restrict__ Wk,
               const float* __restrict__ Wv, const float* __restrict__ Wm,
               const float* __restrict__ W1, const float* __restrict__ W2)
{
  int id = blockIdx.x;
  int type, l, n0, k0, K, N;
  const float* src;
  h16* dst; size_t dstride;
  if (id < 12288){                 // q,k,v,m
    type = id / 3072; id %= 3072;
    l = id / 256; id %= 256;
    n0 = (id / 16) * 32; k0 = (id % 16) * 32;
    K = CC; N = CC;
    switch(type){
      case 0: src=Wq; dst=w_qkv + (size_t)l*NQKV*CC;                 break;
      case 1: src=Wk; dst=w_qkv + (size_t)l*NQKV*CC + (size_t)512*CC; break;
      case 2: src=Wv; dst=w_qkv + (size_t)l*NQKV*CC + (size_t)1024*CC;break;
      default:src=Wm; dst=w_m  + (size_t)l*CC*CC;                    break;
    }
    src += (size_t)l*CC*CC;
    dstride = CC;
  } else if (id < 24576){          // w1
    id -= 12288;
    l = id / 1024; id %= 1024;
    n0 = (id / 32) * 32; k0 = (id % 32) * 32;
    K = C2; N = C2;
    src = W1 + (size_t)l*C2*C2;
    dst = w_1 + (size_t)l*C2*C2;
    dstride = C2;
  } else {                         // w2
    id -= 24576;
    l = id / 512; id %= 512;
    n0 = (id / 32) * 32; k0 = (id % 32) * 32;
    K = C2; N = CC;
    src = W2 + (size_t)l*C2*CC;
    dst = w_2 + (size_t)l*CC*C2;
    dstride = C2;
  }
  __shared__ float tile[32][33];
  const int tx = threadIdx.x & 31, ty = threadIdx.x >> 5;
#pragma unroll
  for (int i = 0; i < 4; i++){
    int r = ty + i*8;
    tile[r][tx] = src[(size_t)(k0+r)*N + n0 + tx];
  }
  __syncthreads();
#pragma unroll
  for (int i = 0; i < 4; i++){
    int r = ty + i*8;
    dst[(size_t)(n0+r)*dstride + k0 + tx] = __float2half(tile[tx][r]);
  }
}

// ---------------- attention: KV split-K (deterministic) ----------------
__global__ __launch_bounds__(256)
void kv_partial(int s0, int s1)
{
  const int slot = blockIdx.z ? s1 : s0;
  const int nh = blockIdx.y, part = blockIdx.x;
  const int n = nh >> 3, h = nh & 7;
  __shared__ float Ks[32][68];
  __shared__ float Vs[32][68];
  const int t = threadIdx.x;
  const int tx = t & 15, ty = t >> 4;
  const float* Kb = g_k[slot] + (size_t)n*LSEQ*CC + h*DD;
  const float* Vb = g_v[slot] + (size_t)n*LSEQ*CC + h*DD;
  float acc[4][4] = {};
  float ksum = 0.f;
  const int send = part*SCHUNK + SCHUNK;
  for (int s0i = part*SCHUNK; s0i < send; s0i += 32){
#pragma unroll
    for (int p = 0; p < 2; p++){
      int idx = t + p*256;
      int r = idx >> 4, c4 = (idx & 15) << 2;
      *(float4*)&Ks[r][c4] = *(const float4*)(Kb + (size_t)(s0i+r)*CC + c4);
      *(float4*)&Vs[r][c4] = *(const float4*)(Vb + (size_t)(s0i+r)*CC + c4);
    }
    __syncthreads();
    if (t < DD){
#pragma unroll
      for (int kk = 0; kk < 32; kk++) ksum += Ks[kk][t];
    }
#pragma unroll
    for (int kk = 0; kk < 32; kk++){
      float4 a = *(const float4*)&Ks[kk][ty*4];
      float4 b = *(const float4*)&Vs[kk][tx*4];
      float ar[4]={a.x,a.y,a.z,a.w}, br[4]={b.x,b.y,b.z,b.w};
#pragma unroll
      for (int i=0;i<4;i++)
#pragma unroll
        for (int j=0;j<4;j++) acc[i][j] = fmaf(ar[i],br[j],acc[i][j]);
    }
    __syncthreads();
  }
  float* dst = g_kvp[slot] + ((size_t)part*NB*HH + nh)*DD*DD;
#pragma unroll
  for (int i=0;i<4;i++)
    *(float4*)&dst[(ty*4+i)*DD + tx*4] =
        make_float4(acc[i][0],acc[i][1],acc[i][2],acc[i][3]);
  if (t < DD) g_ksp[slot][(size_t)part*NB*HH*DD + nh*DD + t] = ksum;
}

__global__ __launch_bounds__(256)
void kv_reduce(int s0, int s1)
{
  const int slot = blockIdx.z ? s1 : s0;
  int i = blockIdx.x*256 + threadIdx.x;
  if (i < NB*HH*DD*DD){
    float s = 0.f;
#pragma unroll
    for (int p=0;p<SPLIT;p++) s += g_kvp[slot][(size_t)p*NB*HH*DD*DD + i];
    g_kv[slot][i] = s;
  }
  if (i < NB*HH*DD){
    float s=0.f;
#pragma unroll
    for (int p=0;p<SPLIT;p++) s += g_ksp[slot][p*NB*HH*DD + i];
    g_ksum[slot][i] = s;
  }
}

// msg = (Q @ KVu) / (Q.Ksum+eps)  -> fp16 hi only
__global__ __launch_bounds__(256)
void msg_kernel(int s0, int s1)
{
  const int slot = blockIdx.z ? s1 : s0;
  const int nh = blockIdx.y;
  const int n = nh >> 3, h = nh & 7;
  const int l0 = blockIdx.x * 64;
  __shared__ float Qs[64][68];
  __shared__ float KVs[64][68];
  __shared__ float ksm[64];
  __shared__ float zrow[64];
  const int t = threadIdx.x;
  const int tx = t & 15, ty = t >> 4;
  const float* Qb  = g_q[slot]  + (size_t)n*LSEQ*CC + h*DD;
  const float* KVb = g_kv[slot] + (size_t)nh*DD*DD;
#pragma unroll
  for (int p=0;p<4;p++){
    int idx = t + p*256;
    int r = idx >> 4, c4 = (idx & 15) << 2;
    float4 q = *(const float4*)(Qb + (size_t)(l0+r)*CC + c4);
    Qs[c4+0][r]=q.x; Qs[c4+1][r]=q.y; Qs[c4+2][r]=q.z; Qs[c4+3][r]=q.w;
    *(float4*)&KVs[r][c4] = *(const float4*)(KVb + r*DD + c4);
  }
  if (t < DD) ksm[t] = g_ksum[slot][nh*DD + t];
  __syncthreads();
  if (t < DD){
    float dn = 0.f;
#pragma unroll
    for (int d=0; d<DD; d++) dn = fmaf(Qs[d][t], ksm[d], dn);
    zrow[t] = 1.0f / (dn + 1e-6f);
  }
  __syncthreads();
  float acc[4][4] = {};
#pragma unroll
  for (int kk=0; kk<DD; kk++){
    float4 a = *(const float4*)&Qs[kk][ty*4];
    float4 b = *(const float4*)&KVs[kk][tx*4];
    float ar[4]={a.x,a.y,a.z,a.w}, br[4]={b.x,b.y,b.z,b.w};
#pragma unroll
    for (int i=0;i<4;i++)
#pragma unroll
      for (int j=0;j<4;j++) acc[i][j] = fmaf(ar[i],br[j],acc[i][j]);
  }
#pragma unroll
  for (int i=0;i<4;i++){
    int m = ty*4+i;
    float zz = zrow[m];
    size_t base = ((size_t)(n*LSEQ + l0 + m))*CC + h*DD + tx*4;
    hstore4(s_mh[slot], base, acc[i][0]*zz, acc[i][1]*zz, acc[i][2]*zz, acc[i][3]*zz);
  }
}

// ---------------- LN kernels ----------------
__device__ __forceinline__ void ln_core(const float4& v, int t, float& mu, float& rs)
{
  float s  = v.x+v.y+v.z+v.w;
  float s2 = v.x*v.x + v.y*v.y + v.z*v.z + v.w*v.w;
  __shared__ float sh[8];
#pragma unroll
  for (int o=16;o>0;o>>=1){
    s  += __shfl_xor_sync(0xffffffffu, s, o);
    s2 += __shfl_xor_sync(0xffffffffu, s2, o);
  }
  if ((t & 31) == 0){ sh[t>>5] = s; sh[4 + (t>>5)] = s2; }
  __syncthreads();
  s  = sh[0]+sh[1]+sh[2]+sh[3];
  s2 = sh[4]+sh[5]+sh[6]+sh[7];
  mu = s * (1.0f/CC);
  float var = s2 * (1.0f/CC) - mu*mu;
  rs = rsqrtf(var + 1e-5f);
}

// LN(g_m[slot]) -> cat{xsel}[:, 512:1024] fp16 hi only
__global__ __launch_bounds__(128)
void ln_to_cat(int x0, int x1, int s0, int s1,
               const float* __restrict__ gamma, const float* __restrict__ beta)
{
  const int xsel = blockIdx.z ? x1 : x0;
  const int slot = blockIdx.z ? s1 : s0;
  const int row = blockIdx.x;
  const int t = threadIdx.x;
  float4 v = *(const float4*)(g_m[slot] + (size_t)row*CC + t*4);
  float mu, rs;
  ln_core(v, t, mu, rs);
  float4 g = *(const float4*)(gamma + t*4);
  float4 b = *(const float4*)(beta + t*4);
  float o0 = (v.x-mu)*rs*g.x + b.x;
  float o1 = (v.y-mu)*rs*g.y + b.y;
  float o2 = (v.z-mu)*rs*g.z + b.z;
  float o3 = (v.w-mu)*rs*g.w + b.w;
  h16* ch = xsel ? s_ch1 : s_ch0;
  hstore4(ch, (size_t)row*C2 + CC + t*4, o0, o1, o2, o3);
}

// x = x + LN(g_k[slot]); writes fp32 x, fp16 hi x-shadow, cat x-half hi
__global__ __launch_bounds__(128)
void ln_res(int x0, int x1, int s0, int s1,
            const float* __restrict__ gamma, const float* __restrict__ beta)
{
  const int xsel = blockIdx.z ? x1 : x0;
  const int slot = blockIdx.z ? s1 : s0;
  const int row = blockIdx.x;
  const int t = threadIdx.x;
  float4 v = *(const float4*)(g_k[slot] + (size_t)row*CC + t*4);
  float mu, rs;
  ln_core(v, t, mu, rs);
  float4 g = *(const float4*)(gamma + t*4);
  float4 b = *(const float4*)(beta + t*4);
  float* x = xsel ? g_f1 : g_f0;
  h16* xh = xsel ? s_xh1 : s_xh0;
  h16* ch = xsel ? s_ch1 : s_ch0;
  float4 r = *(const float4*)(x + (size_t)row*CC + t*4);
  float o0 = (v.x-mu)*rs*g.x + b.x + r.x;
  float o1 = (v.y-mu)*rs*g.y + b.y + r.y;
  float o2 = (v.z-mu)*rs*g.z + b.z + r.z;
  float o3 = (v.w-mu)*rs*g.w + b.w + r.w;
  *(float4*)(x + (size_t)row*CC + t*4) = make_float4(o0,o1,o2,o3);
  hstore4(xh, (size_t)row*CC + t*4, o0, o1, o2, o3);
  hstore4(ch, (size_t)row*C2 + t*4, o0, o1, o2, o3);
}

__global__ __launch_bounds__(256)
void copy_in(const float* __restrict__ f0, const float* __restrict__ f1)
{
  size_t i = (size_t)blockIdx.x*256 + threadIdx.x;
  float4 a = ((const float4*)f0)[i];
  float4 b = ((const float4*)f1)[i];
  ((float4*)g_f0)[i] = a;
  ((float4*)g_f1)[i] = b;
  size_t row = i >> 7, c4 = i & 127;
  hstore4(s_xh0, i*4, a.x, a.y, a.z, a.w);
  hstore4(s_xh1, i*4, b.x, b.y, b.z, b.w);
  hstore4(s_ch0, row*C2 + c4*4, a.x, a.y, a.z, a.w);
  hstore4(s_ch1, row*C2 + c4*4, b.x, b.y, b.z, b.w);
}

__global__ __launch_bounds__(256)
void copy_out(float* __restrict__ out)
{
  size_t i = (size_t)blockIdx.x*256 + threadIdx.x;
  ((float4*)out)[i]          = ((const float4*)g_f0)[i];
  ((float4*)out)[i + ELEMS4] = ((const float4*)g_f1)[i];
}

// ---------------- host-side layer drivers ----------------
static void enc_dual(int layer,
                     const float* gg1, const float* bb1,
                     const float* gg2, const float* bb2)
{
  dim3 blk(256);
  dim3 gq(4, 128, 2);
  dim3 g1k(8, 128, 2);
  mma_gemm_qkv<<<dim3(12,128,2), blk, MMA_SMEM>>>(0, 1, layer, 0, 1, 0);   // QKV fused
  kv_partial<<<dim3(SPLIT, NB*HH, 2), blk>>>(0, 1);
  kv_reduce<<<dim3(512, 1, 2), blk>>>(0, 1);
  msg_kernel<<<dim3(LSEQ/64, NB*HH, 2), blk>>>(0, 1);
  mma_gemm<0><<<gq,  blk, MMA_SMEM>>>(2, 3, 3, layer, 3, 7, CC, CC);       // msg@Wm -> m
  ln_to_cat<<<dim3(ROWS,1,2), 128>>>(0, 1, 0, 1, gg1, bb1);
  mma_gemm<3><<<g1k, blk, MMA_SMEM>>>(4, 5, 4, layer, 0, 1, C2, C2);       // relu(cat@W1) -> t
  mma_gemm<0><<<gq,  blk, MMA_SMEM>>>(6, 7, 5, layer, 1, 5, CC, C2);       // t@W2 -> k
  ln_res<<<dim3(ROWS,1,2), 128>>>(0, 1, 0, 1, gg2, bb2);
}

static void enc_single(int xsel, int ssel, int layer,
                       const float* gg1, const float* bb1,
                       const float* gg2, const float* bb2)
{
  dim3 blk(256);
  dim3 gq(4, 128, 1);
  dim3 g1k(8, 128, 1);
  mma_gemm_qkv<<<dim3(4,128,1), blk, MMA_SMEM>>>(xsel, 0, layer, 0, 0, 0);   // Q only
  mma_gemm_qkv<<<dim3(8,128,1), blk, MMA_SMEM>>>(ssel, 0, layer, 0, 0, 512); // K,V
  kv_partial<<<dim3(SPLIT, NB*HH, 1), blk>>>(0, 0);
  kv_reduce<<<dim3(512, 1, 1), blk>>>(0, 0);
  msg_kernel<<<dim3(LSEQ/64, NB*HH, 1), blk>>>(0, 0);
  mma_gemm<0><<<gq,  blk, MMA_SMEM>>>(2, 0, 3, layer, 3, 0, CC, CC);       // msg@Wm -> m[0]
  ln_to_cat<<<dim3(ROWS,1,1), 128>>>(xsel, 0, 0, 0, gg1, bb1);
  mma_gemm<3><<<g1k, blk, MMA_SMEM>>>(4+xsel, 0, 4, layer, 0, 0, C2, C2);  // -> t[0]
  mma_gemm<0><<<gq,  blk, MMA_SMEM>>>(6, 0, 5, layer, 1, 0, CC, C2);       // -> k[0]
  ln_res<<<dim3(ROWS,1,1), 128>>>(xsel, 0, 0, 0, gg2, bb2);
}

extern "C" void kernel_launch(void* const* d_in, const int* in_sizes, int n_in,
                              void* d_out, int out_size)
{
  (void)in_sizes; (void)n_in; (void)out_size;
  const float* feat0 = (const float*)d_in[0];
  const float* feat1 = (const float*)d_in[1];
  const float* Wq = (const float*)d_in[2];
  const float* Wk = (const float*)d_in[3];
  const float* Wv = (const float*)d_in[4];
  const float* Wm = (const float*)d_in[5];
  const float* W1 = (const float*)d_in[6];
  const float* W2 = (const float*)d_in[7];
  const float* g1 = (const float*)d_in[8];
  const float* b1 = (const float*)d_in[9];
  const float* g2 = (const float*)d_in[10];
  const float* b2 = (const float*)d_in[11];

  cudaFuncSetAttribute((const void*)mma_gemm<0>, cudaFuncAttributeMaxDynamicSharedMemorySize, MMA_SMEM);
  cudaFuncSetAttribute((const void*)mma_gemm<3>, cudaFuncAttributeMaxDynamicSharedMemorySize, MMA_SMEM);
  cudaFuncSetAttribute((const void*)mma_gemm_qkv, cudaFuncAttributeMaxDynamicSharedMemorySize, MMA_SMEM);

  wprep_all<<<30720, 256>>>(Wq, Wk, Wv, Wm, W1, W2);
  copy_in<<<ELEMS4/256, 256>>>(feat0, feat1);

  for (int i = 0; i < NLAYERS; i++){
    const float* gg1 = g1 + (size_t)i*CC;
    const float* bb1 = b1 + (size_t)i*CC;
    const float* gg2 = g2 + (size_t)i*CC;
    const float* bb2 = b2 + (size_t)i*CC;
    if ((i & 1) == 0){
      enc_dual(i, gg1, bb1, gg2, bb2);
    } else {
      enc_single(0, 1, i, gg1, bb1, gg2, bb2);
      enc_single(1, 0, i, gg1, bb1, gg2, bb2);
    }
  }

  copy_out<<<ELEMS4/256, 256>>>((float*)d_out);
}